// round 14
// baseline (speedup 1.0000x reference)
#include <cuda_runtime.h>
#include <cuda_bf16.h>
#include <mma.h>
#include <stdint.h>
#include <math.h>

using namespace nvcuda;

#define NN 8192
#define EE 262144
#define DI 256
#define DL 128

#define H_OFF (NN*DL)
#define LOSS_OFF (NN*DL + NN*DI)

// ------------------------- scratch (__device__ globals; zero-initialized) -------------------------
__device__ float g_xl_e[NN*DL];
__device__ float g_xr_e[NN*DL];
__device__ float g_xl_p[NN*DL];
__device__ float g_xr_p[NN*DL];
__device__ float g_xl_d[NN*DI];
__device__ float g_xr_d[NN*DI];
__device__ float g_g1[NN*DL];
__device__ float g_g2[NN*DL];
__device__ __nv_bfloat16 g_q16[NN*DL];
__device__ __nv_bfloat16 g_p16[NN*DL];
__device__ __nv_bfloat16 g_n16[NN*DL];
__device__ int g_perm[NN];
__device__ unsigned g_bits0[NN];
__device__ unsigned g_bits1[NN];
__device__ float g_bns[3][DL];
__device__ float g_bnq[3][DL];
__device__ float g_acc[2];         // [0]=rec_sum [1]=ctr_sum
__device__ unsigned g_cnt;

// bucket-sort rank scratch
__device__ int g_bh0[NN];
__device__ int g_bh1[NN];
__device__ int g_bs0[NN+1];
__device__ int g_bs1[NN+1];
__device__ int g_bc0[NN];
__device__ int g_bc1[NN];
__device__ int g_si0[NN];
__device__ int g_si1[NN];
__device__ int g_r0[NN];
__device__ int g_r1[NN];

// bf16 split buffers
__device__ __nv_bfloat16 g_Ah[NN*DI];
__device__ __nv_bfloat16 g_Al[NN*DI];
__device__ __nv_bfloat16 g_Bh[DI*512];
__device__ __nv_bfloat16 g_Bl[DI*512];

// CSR scratch (per graph)
__device__ int g_deg_s[NN];
__device__ int g_deg_f[NN];
__device__ int g_cur_s[NN];
__device__ int g_cur_f[NN];
__device__ int g_rp_s[NN+1];
__device__ int g_src_s[EE];
__device__ float g_w_s[EE];
__device__ int g_rp_f[NN+1];
__device__ int g_src_f[EE];
__device__ float g_w_f[EE];

// ------------------------- threefry2x32-20 -------------------------
__device__ __forceinline__ void tfry(uint32_t k0, uint32_t k1, uint32_t x0, uint32_t x1,
                                     uint32_t* o0, uint32_t* o1) {
    uint32_t ks2 = k0 ^ k1 ^ 0x1BD11BDAu;
    x0 += k0; x1 += k1;
#define RR(r) { x0 += x1; x1 = (x1 << (r)) | (x1 >> (32 - (r))); x1 ^= x0; }
    RR(13) RR(15) RR(26) RR(6)  x0 += k1;  x1 += ks2 + 1u;
    RR(17) RR(29) RR(16) RR(24) x0 += ks2; x1 += k0 + 2u;
    RR(13) RR(15) RR(26) RR(6)  x0 += k0;  x1 += k1 + 3u;
    RR(17) RR(29) RR(16) RR(24) x0 += k1;  x1 += ks2 + 4u;
    RR(13) RR(15) RR(26) RR(6)  x0 += ks2; x1 += k0 + 5u;
#undef RR
    *o0 = x0; *o1 = x1;
}

__device__ __forceinline__ void all_keys(uint32_t* ks) {
    uint32_t a0, a1, b0, b1;
    tfry(0u, 42u, 0u, 2u, &a0, &a1);
    tfry(0u, 42u, 1u, 3u, &b0, &b1);
    uint32_t c0, c1, d0, d1;
    tfry(a0, b0, 0u, 2u, &c0, &c1);
    tfry(a0, b0, 1u, 3u, &d0, &d1);
    ks[0] = c1; ks[1] = d1;
    uint32_t e0, e1, f0, f1;
    tfry(c0, d0, 0u, 2u, &e0, &e1);
    tfry(c0, d0, 1u, 3u, &f0, &f1);
    ks[2] = e1; ks[3] = f1;
    ks[4] = a1; ks[5] = b1;
}

// ------------------------- cvt / pack bodies -------------------------
__device__ void cvt4_body(int lb, const float* __restrict__ src,
                          __nv_bfloat16* __restrict__ hi, __nv_bfloat16* __restrict__ lo, int n4) {
    int i = lb * 256 + threadIdx.x;
    if (i >= n4) return;
    float4 a = ((const float4*)src)[i];
    __nv_bfloat162 h0 = __floats2bfloat162_rn(a.x, a.y);
    __nv_bfloat162 h1 = __floats2bfloat162_rn(a.z, a.w);
    float lx = a.x - __bfloat162float(__low2bfloat16(h0));
    float ly = a.y - __bfloat162float(__high2bfloat16(h0));
    float lz = a.z - __bfloat162float(__low2bfloat16(h1));
    float lw = a.w - __bfloat162float(__high2bfloat16(h1));
    ((__nv_bfloat162*)hi)[i * 2] = h0;
    ((__nv_bfloat162*)hi)[i * 2 + 1] = h1;
    ((__nv_bfloat162*)lo)[i * 2] = __floats2bfloat162_rn(lx, ly);
    ((__nv_bfloat162*)lo)[i * 2 + 1] = __floats2bfloat162_rn(lz, lw);
}

__device__ __forceinline__ float keep_val(int k) {
    uint32_t ks[6];
    all_keys(ks);
    uint32_t lo, hi;
    int i = (k < 128) ? k : (k - 128);
    tfry(ks[4], ks[5], (uint32_t)i, (uint32_t)(i + 128), &lo, &hi);
    uint32_t u = (k < 128) ? lo : hi;
    float uf = __uint_as_float((u >> 9) | 0x3f800000u) - 1.0f;
    return (uf >= 0.3f) ? 1.f : 0.f;
}

// ------------------------- prep: hist(2048) | bits(32) | cvt_enc(2048) | packB_enc(512) -------------------------
__global__ void __launch_bounds__(256) k_prep(const int* __restrict__ s_dst, const int* __restrict__ f_dst,
                                              const float* __restrict__ x,
                                              const float* __restrict__ Wl, const float* __restrict__ Wr) {
    int b = blockIdx.x;
    if (b < 1024) {
        int e = b * 256 + threadIdx.x;
        if (e < EE) atomicAdd(&g_deg_s[s_dst[e]], 1);
        return;
    }
    if (b < 2048) {
        int e = (b - 1024) * 256 + threadIdx.x;
        if (e < EE) atomicAdd(&g_deg_f[f_dst[e]], 1);
        return;
    }
    if (b < 2080) {
        int bb = b - 2048;
        int which = (bb < 16) ? 0 : 1;
        int i = (which ? bb - 16 : bb) * 256 + threadIdx.x;
        if (i >= NN / 2) return;
        uint32_t ks[6];
        all_keys(ks);
        uint32_t lo, hi;
        tfry(ks[which * 2], ks[which * 2 + 1], (uint32_t)i, (uint32_t)(i + NN / 2), &lo, &hi);
        unsigned* bits = which ? g_bits1 : g_bits0;
        int* bh = which ? g_bh1 : g_bh0;
        bits[i] = lo; bits[i + NN / 2] = hi;
        atomicAdd(&bh[lo >> 19], 1);
        atomicAdd(&bh[hi >> 19], 1);
        return;
    }
    if (b < 4128) { cvt4_body(b - 2080, x, g_Ah, g_Al, NN * DI / 4); return; }
    int idx = (b - 4128) * 256 + threadIdx.x;
    if (idx >= DI * 512) return;
    int k = idx >> 9, c = idx & 511;
    float v;
    if (c < 128) v = Wl[k * 128 + c];
    else if (c < 256) v = Wr[k * 128 + c - 128];
    else if (c < 384) v = keep_val(k) * Wl[k * 128 + c - 256];
    else v = keep_val(k) * Wr[k * 128 + c - 384];
    __nv_bfloat16 h = __float2bfloat16_rn(v);
    g_Bh[idx] = h;
    g_Bl[idx] = __float2bfloat16_rn(v - __bfloat162float(h));
}

// ------------------------- scans -------------------------
__device__ void scan_body(const int* __restrict__ deg, int* __restrict__ rp, int* __restrict__ cur) {
    __shared__ int wsum[32];
    int tid = threadIdx.x;
    int lane = tid & 31, w = tid >> 5;
    int loc[8]; int s = 0;
#pragma unroll
    for (int i = 0; i < 8; i++) { loc[i] = deg[tid * 8 + i]; s += loc[i]; }
    int ss = s;
#pragma unroll
    for (int o = 1; o < 32; o <<= 1) { int v = __shfl_up_sync(0xffffffffu, ss, o); if (lane >= o) ss += v; }
    if (lane == 31) wsum[w] = ss;
    __syncthreads();
    if (w == 0) {
        int v = wsum[lane];
#pragma unroll
        for (int o = 1; o < 32; o <<= 1) { int u = __shfl_up_sync(0xffffffffu, v, o); if (lane >= o) v += u; }
        wsum[lane] = v;
    }
    __syncthreads();
    int base = ss - s + (w > 0 ? wsum[w - 1] : 0);
#pragma unroll
    for (int i = 0; i < 8; i++) { rp[tid * 8 + i] = base; cur[tid * 8 + i] = base; base += loc[i]; }
    if (tid == 1023) rp[NN] = base;
}

__global__ void __launch_bounds__(1024) k_scan4() {
    int b = blockIdx.x;
    if (b == 0) scan_body(g_deg_s, g_rp_s, g_cur_s);
    else if (b == 1) scan_body(g_deg_f, g_rp_f, g_cur_f);
    else if (b == 2) scan_body(g_bh0, g_bs0, g_bc0);
    else scan_body(g_bh1, g_bs1, g_bc1);
}

// edge fill (2048) + bucket scatter (64)
__global__ void __launch_bounds__(256) k_fill2(const int* __restrict__ s_src, const int* __restrict__ s_dst,
                                               const float* __restrict__ w_h,
                                               const int* __restrict__ f_src, const int* __restrict__ f_dst,
                                               const float* __restrict__ w_h_a) {
    int b = blockIdx.x;
    if (b < 1024) {
        int e = b * 256 + threadIdx.x;
        if (e >= EE) return;
        int d = s_dst[e];
        int pos = atomicAdd(&g_cur_s[d], 1);
        g_src_s[pos] = s_src[e];
        g_w_s[pos] = w_h[e];
    } else if (b < 2048) {
        int e = (b - 1024) * 256 + threadIdx.x;
        if (e >= EE) return;
        int d = f_dst[e];
        int pos = atomicAdd(&g_cur_f[d], 1);
        g_src_f[pos] = f_src[e];
        g_w_f[pos] = w_h_a[e];
    } else if (b < 2080) {
        int i = (b - 2048) * 256 + threadIdx.x;
        if (i >= NN) return;
        int pos = atomicAdd(&g_bc0[g_bits0[i] >> 19], 1);
        g_si0[pos] = i;
    } else {
        int i = (b - 2080) * 256 + threadIdx.x;
        if (i >= NN) return;
        int pos = atomicAdd(&g_bc1[g_bits1[i] >> 19], 1);
        g_si1[pos] = i;
    }
}

// per-element rank via bucket scan (both keys)
__global__ void __launch_bounds__(256) k_rank() {
    int b = blockIdx.x;
    int which = (b < 32) ? 0 : 1;
    int p = (which ? b - 32 : b) * 256 + threadIdx.x;
    if (p >= NN) return;
    const unsigned* bits = which ? g_bits1 : g_bits0;
    const int* si = which ? g_si1 : g_si0;
    const int* bs = which ? g_bs1 : g_bs0;
    int* r = which ? g_r1 : g_r0;
    int i = si[p];
    unsigned bi = bits[i];
    unsigned long long ki = (((unsigned long long)bi) << 13) | (unsigned)i;
    int bkt = bi >> 19;
    int beg = bs[bkt], end = bs[bkt + 1];
    int cnt = 0;
    for (int q = beg; q < end; q++) {
        int j = si[q];
        unsigned long long kj = (((unsigned long long)bits[j]) << 13) | (unsigned)j;
        cnt += (kj < ki);
    }
    r[i] = beg + cnt;
}

// bnstats body
__device__ void bnstats_body(int lb, const float* __restrict__ a0, const float* __restrict__ a1,
                             const float* __restrict__ a2) {
    int y = lb / 32, xb = lb % 32;
    const float* A = (y == 0) ? a0 : (y == 1 ? a1 : a2);
    int c = threadIdx.x % DL;
    int part = threadIdx.x / DL;
    int rbase = xb * 256 + part * 128;
    float s = 0.f, q = 0.f;
    for (int r = 0; r < 128; r++) {
        float v = A[(rbase + r) * DL + c];
        s += v; q += v * v;
    }
    atomicAdd(&g_bns[y][c], s);
    atomicAdd(&g_bnq[y][c], q);
}

// kCP_dec: cvt_dec(1024) | packB_dec(256) | bnstats(96)
__global__ void __launch_bounds__(256) kCP_dec(const float* __restrict__ hiOut,
                                               const float* __restrict__ Wl, const float* __restrict__ Wr,
                                               const float* __restrict__ g1, const float* __restrict__ g2) {
    int b = blockIdx.x;
    if (b < 1024) { cvt4_body(b, hiOut, g_Ah, g_Al, NN * DL / 4); return; }
    if (b < 1280) {
        int idx = (b - 1024) * 256 + threadIdx.x;
        if (idx >= DL * 512) return;
        int k = idx >> 9, c = idx & 511;
        float v = (c < 256) ? Wl[k * 256 + c] : Wr[k * 256 + c - 256];
        __nv_bfloat16 h = __float2bfloat16_rn(v);
        g_Bh[idx] = h;
        g_Bl[idx] = __float2bfloat16_rn(v - __bfloat162float(h));
        return;
    }
    bnstats_body(b - 1280, hiOut, g1, g2);
}

// ------------------------- bf16x3 GEMM, double-buffered k-panels (+ permc rider) -------------------------
#define GEMM_BUF 13824
#define GEMM_SMEM (GEMM_BUF * 2 * 2)
__global__ void __launch_bounds__(256) k_gemm3(const __nv_bfloat16* __restrict__ Ah,
                                               const __nv_bfloat16* __restrict__ Al, int K,
                                               float* o0, float* o1, float* o2, float* o3, int lgw,
                                               int with_permc) {
    int bx = blockIdx.x;
    if (with_permc && bx >= 512) {
        int j = (bx - 512) * 256 + threadIdx.x;
        if (j < NN) g_perm[g_r1[g_r0[j]]] = j;
        return;
    }
    extern __shared__ __nv_bfloat16 gsm[];
    int tid = threadIdx.x;
    int warp = tid >> 5;
    int wm = warp >> 2, wn = warp & 3;
    int row0 = (bx >> 2) * 64, col0 = (bx & 3) * 128;
    wmma::fragment<wmma::accumulator, 16, 16, 16, float> c[2][2];
#pragma unroll
    for (int i = 0; i < 2; i++)
#pragma unroll
        for (int j = 0; j < 2; j++) wmma::fill_fragment(c[i][j], 0.f);
    int r = tid >> 2, q = tid & 3;
    int bk0 = tid >> 4, bq0 = tid & 15;
    int bk1 = (tid + 256) >> 4, bq1 = (tid + 256) & 15;
    int np = K / 32;

    {
        __nv_bfloat16* buf = gsm;
        *(uint4*)&buf[r * 40 + q * 8]            = *(const uint4*)&Ah[(row0 + r) * K + q * 8];
        *(uint4*)&buf[2560 + r * 40 + q * 8]     = *(const uint4*)&Al[(row0 + r) * K + q * 8];
        *(uint4*)&buf[5120 + bk0 * 136 + bq0 * 8] = *(const uint4*)&g_Bh[bk0 * 512 + col0 + bq0 * 8];
        *(uint4*)&buf[5120 + bk1 * 136 + bq1 * 8] = *(const uint4*)&g_Bh[bk1 * 512 + col0 + bq1 * 8];
        *(uint4*)&buf[9472 + bk0 * 136 + bq0 * 8] = *(const uint4*)&g_Bl[bk0 * 512 + col0 + bq0 * 8];
        *(uint4*)&buf[9472 + bk1 * 136 + bq1 * 8] = *(const uint4*)&g_Bl[bk1 * 512 + col0 + bq1 * 8];
    }
    __syncthreads();

    for (int kp = 0; kp < np; kp++) {
        __nv_bfloat16* cur = gsm + (kp & 1) * GEMM_BUF;
        __nv_bfloat16* nxt = gsm + ((kp + 1) & 1) * GEMM_BUF;
        uint4 rAh, rAl, rBh0, rBh1, rBl0, rBl1;
        bool pf = (kp + 1 < np);
        if (pf) {
            int kn = (kp + 1) * 32;
            rAh  = *(const uint4*)&Ah[(row0 + r) * K + kn + q * 8];
            rAl  = *(const uint4*)&Al[(row0 + r) * K + kn + q * 8];
            rBh0 = *(const uint4*)&g_Bh[(kn + bk0) * 512 + col0 + bq0 * 8];
            rBh1 = *(const uint4*)&g_Bh[(kn + bk1) * 512 + col0 + bq1 * 8];
            rBl0 = *(const uint4*)&g_Bl[(kn + bk0) * 512 + col0 + bq0 * 8];
            rBl1 = *(const uint4*)&g_Bl[(kn + bk1) * 512 + col0 + bq1 * 8];
        }
#pragma unroll
        for (int ks = 0; ks < 32; ks += 16) {
            wmma::fragment<wmma::matrix_a, 16, 16, 16, __nv_bfloat16, wmma::row_major> ah[2], al[2];
            wmma::fragment<wmma::matrix_b, 16, 16, 16, __nv_bfloat16, wmma::row_major> bh[2], bl[2];
#pragma unroll
            for (int i = 0; i < 2; i++) {
                wmma::load_matrix_sync(ah[i], &cur[(wm * 32 + i * 16) * 40 + ks], 40);
                wmma::load_matrix_sync(al[i], &cur[2560 + (wm * 32 + i * 16) * 40 + ks], 40);
            }
#pragma unroll
            for (int j = 0; j < 2; j++) {
                wmma::load_matrix_sync(bh[j], &cur[5120 + ks * 136 + wn * 32 + j * 16], 136);
                wmma::load_matrix_sync(bl[j], &cur[9472 + ks * 136 + wn * 32 + j * 16], 136);
            }
#pragma unroll
            for (int i = 0; i < 2; i++)
#pragma unroll
                for (int j = 0; j < 2; j++) {
                    wmma::mma_sync(c[i][j], ah[i], bh[j], c[i][j]);
                    wmma::mma_sync(c[i][j], ah[i], bl[j], c[i][j]);
                    wmma::mma_sync(c[i][j], al[i], bh[j], c[i][j]);
                }
        }
        if (pf) {
            *(uint4*)&nxt[r * 40 + q * 8]             = rAh;
            *(uint4*)&nxt[2560 + r * 40 + q * 8]      = rAl;
            *(uint4*)&nxt[5120 + bk0 * 136 + bq0 * 8] = rBh0;
            *(uint4*)&nxt[5120 + bk1 * 136 + bq1 * 8] = rBh1;
            *(uint4*)&nxt[9472 + bk0 * 136 + bq0 * 8] = rBl0;
            *(uint4*)&nxt[9472 + bk1 * 136 + bq1 * 8] = rBl1;
        }
        __syncthreads();
    }
    float* ob[4] = {o0, o1, o2, o3};
    int W = 1 << lgw, msk = W - 1;
#pragma unroll
    for (int i = 0; i < 2; i++)
#pragma unroll
        for (int j = 0; j < 2; j++) {
            int colg = col0 + wn * 32 + j * 16;
            float* dst = ob[colg >> lgw] + (size_t)(row0 + wm * 32 + i * 16) * W + (colg & msk);
            wmma::store_matrix_sync(dst, c[i][j], W, wmma::mem_row_major);
        }
}

// ------------------------- fused single-pass GAT (warp per node, 4-edge ILP all D) -------------------------
template<int D, bool P>
__device__ void gat_body(int lb, const int* __restrict__ rp, const int* __restrict__ srcS,
                         const float* __restrict__ wS,
                         const float* __restrict__ xl, const float* __restrict__ xr,
                         const float* __restrict__ att,
                         const float* __restrict__ bias, float* __restrict__ out,
                         const int* __restrict__ pidx) {
    constexpr int T = D / 128;
    int node = (lb * 256 + threadIdx.x) >> 5;
    int lane = threadIdx.x & 31;
    if (node >= NN) return;
    int beg = rp[node], end = rp[node + 1];
    int nr = P ? pidx[node] : node;
    const float4* xrp = (const float4*)(xr + nr * D);
    const float4* ap = (const float4*)att;
    float4 xrv[T], av[T], acc[T];
#pragma unroll
    for (int t = 0; t < T; t++) {
        xrv[t] = xrp[lane + t * 32];
        av[t] = ap[lane + t * 32];
        acc[t] = make_float4(0.f, 0.f, 0.f, 0.f);
    }
    float den = 0.f;
    int k = beg;

#define LRELU4(vv, lg) { \
        float ex = vv.x + xrv[t].x; ex = ex > 0.f ? ex : 0.2f * ex; \
        float ey = vv.y + xrv[t].y; ey = ey > 0.f ? ey : 0.2f * ey; \
        float ez = vv.z + xrv[t].z; ez = ez > 0.f ? ez : 0.2f * ez; \
        float ew = vv.w + xrv[t].w; ew = ew > 0.f ? ew : 0.2f * ew; \
        lg += ex * av[t].x + ey * av[t].y + ez * av[t].z + ew * av[t].w; }

    // 4-edge ILP main loop (all D)
    for (; k + 3 < end; k += 4) {
        int s0 = srcS[k], s1 = srcS[k + 1], s2 = srcS[k + 2], s3 = srcS[k + 3];
        if (P) { s0 = pidx[s0]; s1 = pidx[s1]; s2 = pidx[s2]; s3 = pidx[s3]; }
        const float4* xp0 = (const float4*)(xl + s0 * D);
        const float4* xp1 = (const float4*)(xl + s1 * D);
        const float4* xp2 = (const float4*)(xl + s2 * D);
        const float4* xp3 = (const float4*)(xl + s3 * D);
        float4 v0[T], v1[T], v2[T], v3[T];
        float lg0 = 0.f, lg1 = 0.f, lg2 = 0.f, lg3 = 0.f;
#pragma unroll
        for (int t = 0; t < T; t++) {
            v0[t] = xp0[lane + t * 32];
            v1[t] = xp1[lane + t * 32];
            v2[t] = xp2[lane + t * 32];
            v3[t] = xp3[lane + t * 32];
            LRELU4(v0[t], lg0) LRELU4(v1[t], lg1) LRELU4(v2[t], lg2) LRELU4(v3[t], lg3)
        }
#pragma unroll
        for (int o = 16; o; o >>= 1) {
            lg0 += __shfl_xor_sync(0xffffffffu, lg0, o);
            lg1 += __shfl_xor_sync(0xffffffffu, lg1, o);
            lg2 += __shfl_xor_sync(0xffffffffu, lg2, o);
            lg3 += __shfl_xor_sync(0xffffffffu, lg3, o);
        }
        float w0 = __expf(lg0), w1 = __expf(lg1), w2 = __expf(lg2), w3 = __expf(lg3);
        den += (w0 + w1) + (w2 + w3);
        float a0 = w0 * wS[k], a1 = w1 * wS[k + 1], a2 = w2 * wS[k + 2], a3 = w3 * wS[k + 3];
#pragma unroll
        for (int t = 0; t < T; t++) {
            acc[t].x += a0 * v0[t].x + a1 * v1[t].x + a2 * v2[t].x + a3 * v3[t].x;
            acc[t].y += a0 * v0[t].y + a1 * v1[t].y + a2 * v2[t].y + a3 * v3[t].y;
            acc[t].z += a0 * v0[t].z + a1 * v1[t].z + a2 * v2[t].z + a3 * v3[t].z;
            acc[t].w += a0 * v0[t].w + a1 * v1[t].w + a2 * v2[t].w + a3 * v3[t].w;
        }
    }
    // remainder (up to 3 edges)
    for (; k < end; k++) {
        int s = srcS[k];
        if (P) s = pidx[s];
        const float4* xp = (const float4*)(xl + s * D);
        float4 v[T];
        float lg = 0.f;
#pragma unroll
        for (int t = 0; t < T; t++) {
            v[t] = xp[lane + t * 32];
            LRELU4(v[t], lg)
        }
#pragma unroll
        for (int o = 16; o; o >>= 1) lg += __shfl_xor_sync(0xffffffffu, lg, o);
        float w = __expf(lg);
        den += w;
        float a = w * wS[k];
#pragma unroll
        for (int t = 0; t < T; t++) {
            acc[t].x += a * v[t].x; acc[t].y += a * v[t].y;
            acc[t].z += a * v[t].z; acc[t].w += a * v[t].w;
        }
    }
#undef LRELU4
    float inv = 1.f / (den + 1e-16f);
    float4* op = (float4*)(out + node * D);
    const float4* bp = (const float4*)bias;
#pragma unroll
    for (int t = 0; t < T; t++) {
        float4 b = bp[lane + t * 32];
        op[lane + t * 32] = make_float4(acc[t].x * inv + b.x, acc[t].y * inv + b.y,
                                        acc[t].z * inv + b.z, acc[t].w * inv + b.w);
    }
}

// 3 encoder GATs in one kernel
__global__ void __launch_bounds__(256) k_gat_enc(const float* att, const float* bias, float* hi) {
    int b = blockIdx.x;
    int y = b >> 10, lb = b & 1023;
    if (y == 0) gat_body<DL, false>(lb, g_rp_s, g_src_s, g_w_s, g_xl_e, g_xr_e, att, bias, hi, nullptr);
    else if (y == 1) gat_body<DL, false>(lb, g_rp_f, g_src_f, g_w_f, g_xl_p, g_xr_p, att, bias, g_g1, nullptr);
    else gat_body<DL, true>(lb, g_rp_s, g_src_s, g_w_s, g_xl_e, g_xr_e, att, bias, g_g2, g_perm);
}

// ------------------------- BN apply + ELU + L2 + bf16 -------------------------
__device__ void bnl2_body(int lb, const float* __restrict__ a0, const float* __restrict__ a1,
                          const float* __restrict__ a2,
                          const float* __restrict__ gamma, const float* __restrict__ beta) {
    int y = lb / 1024, xb = lb % 1024;
    const float* A = (y == 0) ? a0 : (y == 1 ? a1 : a2);
    __nv_bfloat16* B = (y == 0) ? g_q16 : (y == 1 ? g_p16 : g_n16);
    int gt = xb * 256 + threadIdx.x;
    int row = gt >> 5, lane = threadIdx.x & 31;
    if (row >= NN) return;
    float4 v = ((const float4*)(A + row * DL))[lane];
    float4 sm = ((const float4*)g_bns[y])[lane];
    float4 sq = ((const float4*)g_bnq[y])[lane];
    float4 ga = ((const float4*)gamma)[lane];
    float4 be = ((const float4*)beta)[lane];
    float mu, var, t;
#define BNE(comp) \
    mu = sm.comp * (1.f / NN); var = sq.comp * (1.f / NN) - mu * mu; \
    t = (v.comp - mu) * rsqrtf(var + 1e-5f) * ga.comp + be.comp; \
    v.comp = t > 0.f ? t : expm1f(t);
    BNE(x) BNE(y) BNE(z) BNE(w)
#undef BNE
    float s = v.x * v.x + v.y * v.y + v.z * v.z + v.w * v.w;
#pragma unroll
    for (int o = 16; o; o >>= 1) s += __shfl_xor_sync(0xffffffffu, s, o);
    float inv = 1.f / sqrtf(s);
    __nv_bfloat162* qp = (__nv_bfloat162*)(B + row * DL);
    qp[lane * 2]     = __floats2bfloat162_rn(v.x * inv, v.y * inv);
    qp[lane * 2 + 1] = __floats2bfloat162_rn(v.z * inv, v.w * inv);
}

// k_post: gat_dec(1024) | bnl2(3072)
__global__ void __launch_bounds__(256) k_post(const float* dec_att, const float* dec_b, float* h,
                                              const float* hiOut, const float* bn_g, const float* bn_b) {
    int b = blockIdx.x;
    if (b < 1024) gat_body<DI, false>(b, g_rp_s, g_src_s, g_w_s, g_xl_d, g_xr_d, dec_att, dec_b, h, nullptr);
    else bnl2_body(b - 1024, hiOut, g_g1, g_g2, bn_g, bn_b);
}

// ------------------------- InfoNCE (mma.sync, cp.async prefetch) + rec rider -------------------------
#define QS_W 136
#define NCE_SMEM ((64*QS_W + 2*128*QS_W) * 2)
__device__ __forceinline__ void mma16816(float* c, uint32_t a0, uint32_t a1, uint32_t a2, uint32_t a3,
                                         uint32_t b0, uint32_t b1) {
    asm volatile(
        "mma.sync.aligned.m16n8k16.row.col.f32.bf16.bf16.f32 "
        "{%0,%1,%2,%3}, {%4,%5,%6,%7}, {%8,%9}, {%0,%1,%2,%3};"
        : "+f"(c[0]), "+f"(c[1]), "+f"(c[2]), "+f"(c[3])
        : "r"(a0), "r"(a1), "r"(a2), "r"(a3), "r"(b0), "r"(b1));
}
__device__ __forceinline__ void cpa16(uint32_t dst, const void* src) {
    asm volatile("cp.async.cg.shared.global [%0], [%1], 16;" :: "r"(dst), "l"(src));
}

__device__ void finalize_arrive(float* loss, unsigned total) {
    __threadfence();
    unsigned old = atomicInc(&g_cnt, total - 1u);
    if (old == total - 1u) {
        __threadfence();
        loss[0] = g_acc[0] * (1.f / (float)(NN * DI)) + 0.2f * (g_acc[1] * (1.f / (float)NN));
        g_acc[0] = 0.f; g_acc[1] = 0.f;
    }
}

// blocks [0,128): NCE; blocks [128,384): rec + re-zero
__global__ void k_ncerec(const float* __restrict__ x, const float* __restrict__ h,
                         float* __restrict__ loss) {
    int tid = threadIdx.x;
    if (blockIdx.x >= 128) {
        // ---- rec role ----
        int rb = blockIdx.x - 128;
        float s = 0.f;
        for (int i = rb * 256 + tid; i < NN * DI; i += 256 * 256) {
            float d = x[i] - h[i];
            s += d * d;
        }
#pragma unroll
        for (int o = 16; o; o >>= 1) s += __shfl_down_sync(0xffffffffu, s, o);
        __shared__ float red[8];
        int lane = tid & 31, wid = tid >> 5;
        if (lane == 0) red[wid] = s;
        __syncthreads();
        if (tid < 32) {
            int idx = rb * 32 + tid;
            g_deg_s[idx] = 0; g_deg_f[idx] = 0;
            g_bh0[idx] = 0;   g_bh1[idx] = 0;
        }
        if (rb < 3 && tid >= 32 && tid < 32 + DL) {
            g_bns[rb][tid - 32] = 0.f;
            g_bnq[rb][tid - 32] = 0.f;
        }
        __syncthreads();
        if (tid == 0) {
            float t = 0.f;
            for (int i = 0; i < 8; i++) t += red[i];
            atomicAdd(&g_acc[0], t);
            finalize_arrive(loss, 384u);
        }
        return;
    }
    // ---- NCE role ----
    extern __shared__ char smraw[];
    __nv_bfloat16* qs = (__nv_bfloat16*)smraw;                 // [64][136]
    __nv_bfloat16* ns0 = qs + 64 * QS_W;                       // [128][136]
    __nv_bfloat16* ns1 = ns0 + 128 * QS_W;                     // [128][136]
    __shared__ float pos2[64];
    __shared__ float rowS[64];
    __shared__ float blksum;
    int warp = tid >> 5, lane = tid & 31;
    int g = lane >> 2, tig = lane & 3;
    int r0 = blockIdx.x * 64;
    uint32_t ns0a = (uint32_t)__cvta_generic_to_shared(ns0);
    uint32_t ns1a = (uint32_t)__cvta_generic_to_shared(ns1);

    {
        const uint4* src = (const uint4*)(g_q16 + r0 * DL);
        uint4* dst4 = (uint4*)qs;
#pragma unroll
        for (int i = tid; i < 64 * 16; i += 256) {
            int row = i >> 4, c = i & 15;
            dst4[row * 17 + c] = src[i];
        }
    }
    // preload ns tile 0 via cp.async
    {
        const uint4* src = (const uint4*)g_n16;
#pragma unroll
        for (int i = tid; i < 128 * 16; i += 256) {
            int row = i >> 4, c = i & 15;
            cpa16(ns0a + (row * 17 + c) * 16, src + i);
        }
        asm volatile("cp.async.commit_group;");
    }
    if (tid < 64) rowS[tid] = 0.f;
    if (tid == 0) blksum = 0.f;
    __syncthreads();

    {
        int row = tid >> 2, part = tid & 3;
        float s = 0.f;
        const __nv_bfloat16* pr = g_p16 + (r0 + row) * DL;
        for (int k = part * 32; k < part * 32 + 32; k++)
            s += __bfloat162float(qs[row * QS_W + k]) * __bfloat162float(pr[k]);
        s += __shfl_down_sync(0xffffffffu, s, 1);
        s += __shfl_down_sync(0xffffffffu, s, 2);
        if (part == 0) pos2[row] = 2.f * s;
    }
    asm volatile("cp.async.wait_group 0;");
    __syncthreads();

    int wm = (warp & 3) * 16;
    int wn = (warp >> 2) * 64;
    int rA = wm + g;
    float s0 = 0.f, s1 = 0.f;

    for (int it = 0; it < 64; it++) {
        __nv_bfloat16* cur = (it & 1) ? ns1 : ns0;
        uint32_t nxta = (it & 1) ? ns0a : ns1a;
        if (it + 1 < 64) {
            const uint4* src = (const uint4*)(g_n16 + (it + 1) * 128 * DL);
#pragma unroll
            for (int i = tid; i < 128 * 16; i += 256) {
                int row = i >> 4, c = i & 15;
                cpa16(nxta + (row * 17 + c) * 16, src + i);
            }
            asm volatile("cp.async.commit_group;");
        }
        float c[8][4];
#pragma unroll
        for (int j = 0; j < 8; j++)
#pragma unroll
            for (int q = 0; q < 4; q++) c[j][q] = 0.f;
#pragma unroll
        for (int k0 = 0; k0 < 8; k0++) {
            int kb = k0 * 16;
            uint32_t a0 = *(const uint32_t*)&qs[rA * QS_W + kb + 2 * tig];
            uint32_t a1 = *(const uint32_t*)&qs[(rA + 8) * QS_W + kb + 2 * tig];
            uint32_t a2 = *(const uint32_t*)&qs[rA * QS_W + kb + 8 + 2 * tig];
            uint32_t a3 = *(const uint32_t*)&qs[(rA + 8) * QS_W + kb + 8 + 2 * tig];
#pragma unroll
            for (int j = 0; j < 8; j++) {
                int n = wn + j * 8 + g;
                uint32_t b0 = *(const uint32_t*)&cur[n * QS_W + kb + 2 * tig];
                uint32_t b1 = *(const uint32_t*)&cur[n * QS_W + kb + 8 + 2 * tig];
                mma16816(c[j], a0, a1, a2, a3, b0, b1);
            }
        }
#pragma unroll
        for (int j = 0; j < 8; j++) {
            s0 += __expf(2.f * c[j][0]) + __expf(2.f * c[j][1]);
            s1 += __expf(2.f * c[j][2]) + __expf(2.f * c[j][3]);
        }
        asm volatile("cp.async.wait_group 0;");
        __syncthreads();
    }
    s0 += __shfl_xor_sync(0xffffffffu, s0, 1);
    s0 += __shfl_xor_sync(0xffffffffu, s0, 2);
    s1 += __shfl_xor_sync(0xffffffffu, s1, 1);
    s1 += __shfl_xor_sync(0xffffffffu, s1, 2);
    if (tig == 0) {
        atomicAdd(&rowS[rA], s0);
        atomicAdd(&rowS[rA + 8], s1);
    }
    __syncthreads();
    if (tid < 64) {
        float S = rowS[tid];
        float p = pos2[tid];
        float l = logf(S + __expf(p)) - p;
        atomicAdd(&blksum, l);
    }
    __syncthreads();
    if (tid == 0) {
        atomicAdd(&g_acc[1], blksum);
        finalize_arrive(loss, 384u);
    }
}

// ------------------------- host orchestration (single stream) -------------------------
extern "C" void kernel_launch(void* const* d_in, const int* in_sizes, int n_in,
                              void* d_out, int out_size) {
    (void)in_sizes; (void)n_in; (void)out_size;
    const float* x       = (const float*)d_in[0];
    const int*   gsi     = (const int*)d_in[1];
    const int*   gfi     = (const int*)d_in[2];
    const float* w_h     = (const float*)d_in[3];
    const float* w_h_a   = (const float*)d_in[4];
    const float* enc_Wl  = (const float*)d_in[5];
    const float* enc_Wr  = (const float*)d_in[6];
    const float* enc_att = (const float*)d_in[7];
    const float* enc_b   = (const float*)d_in[8];
    const float* dec_Wl  = (const float*)d_in[9];
    const float* dec_Wr  = (const float*)d_in[10];
    const float* dec_att = (const float*)d_in[11];
    const float* dec_b   = (const float*)d_in[12];
    const float* bn_g    = (const float*)d_in[13];
    const float* bn_b    = (const float*)d_in[14];

    float* out  = (float*)d_out;
    float* hi   = out;
    float* h    = out + H_OFF;
    float* loss = out + LOSS_OFF;

    const int* s_src = gsi;
    const int* s_dst = gsi + EE;
    const int* f_src = gfi;
    const int* f_dst = gfi + EE;

    cudaFuncSetAttribute(k_ncerec, cudaFuncAttributeMaxDynamicSharedMemorySize, NCE_SMEM);
    cudaFuncSetAttribute(k_gemm3, cudaFuncAttributeMaxDynamicSharedMemorySize, GEMM_SMEM);

    void* p;
    cudaGetSymbolAddress(&p, g_Ah); __nv_bfloat16* Ah = (__nv_bfloat16*)p;
    cudaGetSymbolAddress(&p, g_Al); __nv_bfloat16* Al = (__nv_bfloat16*)p;
    cudaGetSymbolAddress(&p, g_xl_e); float* xle = (float*)p;
    cudaGetSymbolAddress(&p, g_xr_e); float* xre = (float*)p;
    cudaGetSymbolAddress(&p, g_xl_p); float* xlp = (float*)p;
    cudaGetSymbolAddress(&p, g_xr_p); float* xrp = (float*)p;
    cudaGetSymbolAddress(&p, g_xl_d); float* xld = (float*)p;
    cudaGetSymbolAddress(&p, g_xr_d); float* xrd = (float*)p;
    cudaGetSymbolAddress(&p, g_g1); float* gg1 = (float*)p;
    cudaGetSymbolAddress(&p, g_g2); float* gg2 = (float*)p;

    k_prep<<<4640, 256>>>(s_dst, f_dst, x, enc_Wl, enc_Wr);
    k_scan4<<<4, 1024>>>();
    k_fill2<<<2112, 256>>>(s_src, s_dst, w_h, f_src, f_dst, w_h_a);
    k_rank<<<64, 256>>>();

    k_gemm3<<<544, 256, GEMM_SMEM>>>(Ah, Al, DI, xle, xre, xlp, xrp, 7, 1);
    k_gat_enc<<<3072, 256>>>(enc_att, enc_b, hi);

    kCP_dec<<<1376, 256>>>(hi, dec_Wl, dec_Wr, gg1, gg2);
    k_gemm3<<<512, 256, GEMM_SMEM>>>(Ah, Al, DL, xld, xrd, xld, xrd, 8, 0);
    k_post<<<4096, 256>>>(dec_att, dec_b, h, hi, bn_g, bn_b);

    k_ncerec<<<384, 256, NCE_SMEM>>>(x, h, loss);
}

// round 15
// speedup vs baseline: 1.1955x; 1.1955x over previous
#include <cuda_runtime.h>
#include <cuda_bf16.h>
#include <mma.h>
#include <stdint.h>
#include <math.h>

using namespace nvcuda;

#define NN 8192
#define EE 262144
#define DI 256
#define DL 128

#define H_OFF (NN*DL)
#define LOSS_OFF (NN*DL + NN*DI)

// ------------------------- scratch (__device__ globals; zero-initialized) -------------------------
__device__ float g_xl_e[NN*DL];
__device__ float g_xr_e[NN*DL];
__device__ float g_xl_p[NN*DL];
__device__ float g_xr_p[NN*DL];
__device__ float g_xl_d[NN*DI];
__device__ float g_xr_d[NN*DI];
__device__ float g_g1[NN*DL];
__device__ float g_g2[NN*DL];
__device__ __nv_bfloat16 g_q16[NN*DL];
__device__ __nv_bfloat16 g_p16[NN*DL];
__device__ __nv_bfloat16 g_n16[NN*DL];
__device__ int g_perm[NN];
__device__ unsigned g_bits0[NN];
__device__ unsigned g_bits1[NN];
__device__ float g_bns[3][DL];
__device__ float g_bnq[3][DL];
__device__ float g_acc[2];         // [0]=rec_sum [1]=ctr_sum
__device__ unsigned g_cnt;

// bucket-sort rank scratch
__device__ int g_bh0[NN];
__device__ int g_bh1[NN];
__device__ int g_bs0[NN+1];
__device__ int g_bs1[NN+1];
__device__ int g_bc0[NN];
__device__ int g_bc1[NN];
__device__ int g_si0[NN];
__device__ int g_si1[NN];
__device__ int g_r0[NN];
__device__ int g_r1[NN];

// bf16 split buffers
__device__ __nv_bfloat16 g_Ah[NN*DI];
__device__ __nv_bfloat16 g_Al[NN*DI];
__device__ __nv_bfloat16 g_Bh[DI*512];
__device__ __nv_bfloat16 g_Bl[DI*512];

// CSR scratch (per graph)
__device__ int g_deg_s[NN];
__device__ int g_deg_f[NN];
__device__ int g_cur_s[NN];
__device__ int g_cur_f[NN];
__device__ int g_rp_s[NN+1];
__device__ int g_src_s[EE];
__device__ float g_w_s[EE];
__device__ int g_rp_f[NN+1];
__device__ int g_src_f[EE];
__device__ float g_w_f[EE];

// ------------------------- threefry2x32-20 -------------------------
__device__ __forceinline__ void tfry(uint32_t k0, uint32_t k1, uint32_t x0, uint32_t x1,
                                     uint32_t* o0, uint32_t* o1) {
    uint32_t ks2 = k0 ^ k1 ^ 0x1BD11BDAu;
    x0 += k0; x1 += k1;
#define RR(r) { x0 += x1; x1 = (x1 << (r)) | (x1 >> (32 - (r))); x1 ^= x0; }
    RR(13) RR(15) RR(26) RR(6)  x0 += k1;  x1 += ks2 + 1u;
    RR(17) RR(29) RR(16) RR(24) x0 += ks2; x1 += k0 + 2u;
    RR(13) RR(15) RR(26) RR(6)  x0 += k0;  x1 += k1 + 3u;
    RR(17) RR(29) RR(16) RR(24) x0 += k1;  x1 += ks2 + 4u;
    RR(13) RR(15) RR(26) RR(6)  x0 += ks2; x1 += k0 + 5u;
#undef RR
    *o0 = x0; *o1 = x1;
}

__device__ __forceinline__ void all_keys(uint32_t* ks) {
    uint32_t a0, a1, b0, b1;
    tfry(0u, 42u, 0u, 2u, &a0, &a1);
    tfry(0u, 42u, 1u, 3u, &b0, &b1);
    uint32_t c0, c1, d0, d1;
    tfry(a0, b0, 0u, 2u, &c0, &c1);
    tfry(a0, b0, 1u, 3u, &d0, &d1);
    ks[0] = c1; ks[1] = d1;
    uint32_t e0, e1, f0, f1;
    tfry(c0, d0, 0u, 2u, &e0, &e1);
    tfry(c0, d0, 1u, 3u, &f0, &f1);
    ks[2] = e1; ks[3] = f1;
    ks[4] = a1; ks[5] = b1;
}

// ------------------------- cvt / pack bodies -------------------------
__device__ void cvt4_body(int lb, const float* __restrict__ src,
                          __nv_bfloat16* __restrict__ hi, __nv_bfloat16* __restrict__ lo, int n4) {
    int i = lb * 256 + threadIdx.x;
    if (i >= n4) return;
    float4 a = ((const float4*)src)[i];
    __nv_bfloat162 h0 = __floats2bfloat162_rn(a.x, a.y);
    __nv_bfloat162 h1 = __floats2bfloat162_rn(a.z, a.w);
    float lx = a.x - __bfloat162float(__low2bfloat16(h0));
    float ly = a.y - __bfloat162float(__high2bfloat16(h0));
    float lz = a.z - __bfloat162float(__low2bfloat16(h1));
    float lw = a.w - __bfloat162float(__high2bfloat16(h1));
    ((__nv_bfloat162*)hi)[i * 2] = h0;
    ((__nv_bfloat162*)hi)[i * 2 + 1] = h1;
    ((__nv_bfloat162*)lo)[i * 2] = __floats2bfloat162_rn(lx, ly);
    ((__nv_bfloat162*)lo)[i * 2 + 1] = __floats2bfloat162_rn(lz, lw);
}

__device__ __forceinline__ float keep_val(int k) {
    uint32_t ks[6];
    all_keys(ks);
    uint32_t lo, hi;
    int i = (k < 128) ? k : (k - 128);
    tfry(ks[4], ks[5], (uint32_t)i, (uint32_t)(i + 128), &lo, &hi);
    uint32_t u = (k < 128) ? lo : hi;
    float uf = __uint_as_float((u >> 9) | 0x3f800000u) - 1.0f;
    return (uf >= 0.3f) ? 1.f : 0.f;
}

// ------------------------- prep: hist(2048) | bits(32) | cvt_enc(2048) | packB_enc(512) -------------------------
__global__ void __launch_bounds__(256) k_prep(const int* __restrict__ s_dst, const int* __restrict__ f_dst,
                                              const float* __restrict__ x,
                                              const float* __restrict__ Wl, const float* __restrict__ Wr) {
    int b = blockIdx.x;
    if (b < 1024) {
        int e = b * 256 + threadIdx.x;
        if (e < EE) atomicAdd(&g_deg_s[s_dst[e]], 1);
        return;
    }
    if (b < 2048) {
        int e = (b - 1024) * 256 + threadIdx.x;
        if (e < EE) atomicAdd(&g_deg_f[f_dst[e]], 1);
        return;
    }
    if (b < 2080) {
        int bb = b - 2048;
        int which = (bb < 16) ? 0 : 1;
        int i = (which ? bb - 16 : bb) * 256 + threadIdx.x;
        if (i >= NN / 2) return;
        uint32_t ks[6];
        all_keys(ks);
        uint32_t lo, hi;
        tfry(ks[which * 2], ks[which * 2 + 1], (uint32_t)i, (uint32_t)(i + NN / 2), &lo, &hi);
        unsigned* bits = which ? g_bits1 : g_bits0;
        int* bh = which ? g_bh1 : g_bh0;
        bits[i] = lo; bits[i + NN / 2] = hi;
        atomicAdd(&bh[lo >> 19], 1);
        atomicAdd(&bh[hi >> 19], 1);
        return;
    }
    if (b < 4128) { cvt4_body(b - 2080, x, g_Ah, g_Al, NN * DI / 4); return; }
    int idx = (b - 4128) * 256 + threadIdx.x;
    if (idx >= DI * 512) return;
    int k = idx >> 9, c = idx & 511;
    float v;
    if (c < 128) v = Wl[k * 128 + c];
    else if (c < 256) v = Wr[k * 128 + c - 128];
    else if (c < 384) v = keep_val(k) * Wl[k * 128 + c - 256];
    else v = keep_val(k) * Wr[k * 128 + c - 384];
    __nv_bfloat16 h = __float2bfloat16_rn(v);
    g_Bh[idx] = h;
    g_Bl[idx] = __float2bfloat16_rn(v - __bfloat162float(h));
}

// ------------------------- scans -------------------------
__device__ void scan_body(const int* __restrict__ deg, int* __restrict__ rp, int* __restrict__ cur) {
    __shared__ int wsum[32];
    int tid = threadIdx.x;
    int lane = tid & 31, w = tid >> 5;
    int loc[8]; int s = 0;
#pragma unroll
    for (int i = 0; i < 8; i++) { loc[i] = deg[tid * 8 + i]; s += loc[i]; }
    int ss = s;
#pragma unroll
    for (int o = 1; o < 32; o <<= 1) { int v = __shfl_up_sync(0xffffffffu, ss, o); if (lane >= o) ss += v; }
    if (lane == 31) wsum[w] = ss;
    __syncthreads();
    if (w == 0) {
        int v = wsum[lane];
#pragma unroll
        for (int o = 1; o < 32; o <<= 1) { int u = __shfl_up_sync(0xffffffffu, v, o); if (lane >= o) v += u; }
        wsum[lane] = v;
    }
    __syncthreads();
    int base = ss - s + (w > 0 ? wsum[w - 1] : 0);
#pragma unroll
    for (int i = 0; i < 8; i++) { rp[tid * 8 + i] = base; cur[tid * 8 + i] = base; base += loc[i]; }
    if (tid == 1023) rp[NN] = base;
}

__global__ void __launch_bounds__(1024) k_scan4() {
    int b = blockIdx.x;
    if (b == 0) scan_body(g_deg_s, g_rp_s, g_cur_s);
    else if (b == 1) scan_body(g_deg_f, g_rp_f, g_cur_f);
    else if (b == 2) scan_body(g_bh0, g_bs0, g_bc0);
    else scan_body(g_bh1, g_bs1, g_bc1);
}

// edge fill (2048) + bucket scatter (64)
__global__ void __launch_bounds__(256) k_fill2(const int* __restrict__ s_src, const int* __restrict__ s_dst,
                                               const float* __restrict__ w_h,
                                               const int* __restrict__ f_src, const int* __restrict__ f_dst,
                                               const float* __restrict__ w_h_a) {
    int b = blockIdx.x;
    if (b < 1024) {
        int e = b * 256 + threadIdx.x;
        if (e >= EE) return;
        int d = s_dst[e];
        int pos = atomicAdd(&g_cur_s[d], 1);
        g_src_s[pos] = s_src[e];
        g_w_s[pos] = w_h[e];
    } else if (b < 2048) {
        int e = (b - 1024) * 256 + threadIdx.x;
        if (e >= EE) return;
        int d = f_dst[e];
        int pos = atomicAdd(&g_cur_f[d], 1);
        g_src_f[pos] = f_src[e];
        g_w_f[pos] = w_h_a[e];
    } else if (b < 2080) {
        int i = (b - 2048) * 256 + threadIdx.x;
        if (i >= NN) return;
        int pos = atomicAdd(&g_bc0[g_bits0[i] >> 19], 1);
        g_si0[pos] = i;
    } else {
        int i = (b - 2080) * 256 + threadIdx.x;
        if (i >= NN) return;
        int pos = atomicAdd(&g_bc1[g_bits1[i] >> 19], 1);
        g_si1[pos] = i;
    }
}

// per-element rank via bucket scan (both keys)
__global__ void __launch_bounds__(256) k_rank() {
    int b = blockIdx.x;
    int which = (b < 32) ? 0 : 1;
    int p = (which ? b - 32 : b) * 256 + threadIdx.x;
    if (p >= NN) return;
    const unsigned* bits = which ? g_bits1 : g_bits0;
    const int* si = which ? g_si1 : g_si0;
    const int* bs = which ? g_bs1 : g_bs0;
    int* r = which ? g_r1 : g_r0;
    int i = si[p];
    unsigned bi = bits[i];
    unsigned long long ki = (((unsigned long long)bi) << 13) | (unsigned)i;
    int bkt = bi >> 19;
    int beg = bs[bkt], end = bs[bkt + 1];
    int cnt = 0;
    for (int q = beg; q < end; q++) {
        int j = si[q];
        unsigned long long kj = (((unsigned long long)bits[j]) << 13) | (unsigned)j;
        cnt += (kj < ki);
    }
    r[i] = beg + cnt;
}

// bnstats body
__device__ void bnstats_body(int lb, const float* __restrict__ a0, const float* __restrict__ a1,
                             const float* __restrict__ a2) {
    int y = lb / 32, xb = lb % 32;
    const float* A = (y == 0) ? a0 : (y == 1 ? a1 : a2);
    int c = threadIdx.x % DL;
    int part = threadIdx.x / DL;
    int rbase = xb * 256 + part * 128;
    float s = 0.f, q = 0.f;
    for (int r = 0; r < 128; r++) {
        float v = A[(rbase + r) * DL + c];
        s += v; q += v * v;
    }
    atomicAdd(&g_bns[y][c], s);
    atomicAdd(&g_bnq[y][c], q);
}

// kCP_dec: cvt_dec(1024) | packB_dec(256) | bnstats(96)
__global__ void __launch_bounds__(256) kCP_dec(const float* __restrict__ hiOut,
                                               const float* __restrict__ Wl, const float* __restrict__ Wr,
                                               const float* __restrict__ g1, const float* __restrict__ g2) {
    int b = blockIdx.x;
    if (b < 1024) { cvt4_body(b, hiOut, g_Ah, g_Al, NN * DL / 4); return; }
    if (b < 1280) {
        int idx = (b - 1024) * 256 + threadIdx.x;
        if (idx >= DL * 512) return;
        int k = idx >> 9, c = idx & 511;
        float v = (c < 256) ? Wl[k * 256 + c] : Wr[k * 256 + c - 256];
        __nv_bfloat16 h = __float2bfloat16_rn(v);
        g_Bh[idx] = h;
        g_Bl[idx] = __float2bfloat16_rn(v - __bfloat162float(h));
        return;
    }
    bnstats_body(b - 1280, hiOut, g1, g2);
}

// ------------------------- bf16x3 GEMM, double-buffered k-panels (+ permc rider) -------------------------
#define GEMM_BUF 13824
#define GEMM_SMEM (GEMM_BUF * 2 * 2)
__global__ void __launch_bounds__(256) k_gemm3(const __nv_bfloat16* __restrict__ Ah,
                                               const __nv_bfloat16* __restrict__ Al, int K,
                                               float* o0, float* o1, float* o2, float* o3, int lgw,
                                               int with_permc) {
    int bx = blockIdx.x;
    if (with_permc && bx >= 512) {
        int j = (bx - 512) * 256 + threadIdx.x;
        if (j < NN) g_perm[g_r1[g_r0[j]]] = j;
        return;
    }
    extern __shared__ __nv_bfloat16 gsm[];
    int tid = threadIdx.x;
    int warp = tid >> 5;
    int wm = warp >> 2, wn = warp & 3;
    int row0 = (bx >> 2) * 64, col0 = (bx & 3) * 128;
    wmma::fragment<wmma::accumulator, 16, 16, 16, float> c[2][2];
#pragma unroll
    for (int i = 0; i < 2; i++)
#pragma unroll
        for (int j = 0; j < 2; j++) wmma::fill_fragment(c[i][j], 0.f);
    int r = tid >> 2, q = tid & 3;
    int bk0 = tid >> 4, bq0 = tid & 15;
    int bk1 = (tid + 256) >> 4, bq1 = (tid + 256) & 15;
    int np = K / 32;

    {
        __nv_bfloat16* buf = gsm;
        *(uint4*)&buf[r * 40 + q * 8]            = *(const uint4*)&Ah[(row0 + r) * K + q * 8];
        *(uint4*)&buf[2560 + r * 40 + q * 8]     = *(const uint4*)&Al[(row0 + r) * K + q * 8];
        *(uint4*)&buf[5120 + bk0 * 136 + bq0 * 8] = *(const uint4*)&g_Bh[bk0 * 512 + col0 + bq0 * 8];
        *(uint4*)&buf[5120 + bk1 * 136 + bq1 * 8] = *(const uint4*)&g_Bh[bk1 * 512 + col0 + bq1 * 8];
        *(uint4*)&buf[9472 + bk0 * 136 + bq0 * 8] = *(const uint4*)&g_Bl[bk0 * 512 + col0 + bq0 * 8];
        *(uint4*)&buf[9472 + bk1 * 136 + bq1 * 8] = *(const uint4*)&g_Bl[bk1 * 512 + col0 + bq1 * 8];
    }
    __syncthreads();

    for (int kp = 0; kp < np; kp++) {
        __nv_bfloat16* cur = gsm + (kp & 1) * GEMM_BUF;
        __nv_bfloat16* nxt = gsm + ((kp + 1) & 1) * GEMM_BUF;
        uint4 rAh, rAl, rBh0, rBh1, rBl0, rBl1;
        bool pf = (kp + 1 < np);
        if (pf) {
            int kn = (kp + 1) * 32;
            rAh  = *(const uint4*)&Ah[(row0 + r) * K + kn + q * 8];
            rAl  = *(const uint4*)&Al[(row0 + r) * K + kn + q * 8];
            rBh0 = *(const uint4*)&g_Bh[(kn + bk0) * 512 + col0 + bq0 * 8];
            rBh1 = *(const uint4*)&g_Bh[(kn + bk1) * 512 + col0 + bq1 * 8];
            rBl0 = *(const uint4*)&g_Bl[(kn + bk0) * 512 + col0 + bq0 * 8];
            rBl1 = *(const uint4*)&g_Bl[(kn + bk1) * 512 + col0 + bq1 * 8];
        }
#pragma unroll
        for (int ks = 0; ks < 32; ks += 16) {
            wmma::fragment<wmma::matrix_a, 16, 16, 16, __nv_bfloat16, wmma::row_major> ah[2], al[2];
            wmma::fragment<wmma::matrix_b, 16, 16, 16, __nv_bfloat16, wmma::row_major> bh[2], bl[2];
#pragma unroll
            for (int i = 0; i < 2; i++) {
                wmma::load_matrix_sync(ah[i], &cur[(wm * 32 + i * 16) * 40 + ks], 40);
                wmma::load_matrix_sync(al[i], &cur[2560 + (wm * 32 + i * 16) * 40 + ks], 40);
            }
#pragma unroll
            for (int j = 0; j < 2; j++) {
                wmma::load_matrix_sync(bh[j], &cur[5120 + ks * 136 + wn * 32 + j * 16], 136);
                wmma::load_matrix_sync(bl[j], &cur[9472 + ks * 136 + wn * 32 + j * 16], 136);
            }
#pragma unroll
            for (int i = 0; i < 2; i++)
#pragma unroll
                for (int j = 0; j < 2; j++) {
                    wmma::mma_sync(c[i][j], ah[i], bh[j], c[i][j]);
                    wmma::mma_sync(c[i][j], ah[i], bl[j], c[i][j]);
                    wmma::mma_sync(c[i][j], al[i], bh[j], c[i][j]);
                }
        }
        if (pf) {
            *(uint4*)&nxt[r * 40 + q * 8]             = rAh;
            *(uint4*)&nxt[2560 + r * 40 + q * 8]      = rAl;
            *(uint4*)&nxt[5120 + bk0 * 136 + bq0 * 8] = rBh0;
            *(uint4*)&nxt[5120 + bk1 * 136 + bq1 * 8] = rBh1;
            *(uint4*)&nxt[9472 + bk0 * 136 + bq0 * 8] = rBl0;
            *(uint4*)&nxt[9472 + bk1 * 136 + bq1 * 8] = rBl1;
        }
        __syncthreads();
    }
    float* ob[4] = {o0, o1, o2, o3};
    int W = 1 << lgw, msk = W - 1;
#pragma unroll
    for (int i = 0; i < 2; i++)
#pragma unroll
        for (int j = 0; j < 2; j++) {
            int colg = col0 + wn * 32 + j * 16;
            float* dst = ob[colg >> lgw] + (size_t)(row0 + wm * 32 + i * 16) * W + (colg & msk);
            wmma::store_matrix_sync(dst, c[i][j], W, wmma::mem_row_major);
        }
}

// ------------------------- fused single-pass GAT (warp per node, 4-edge D=128 / 2-edge D=256) -------------------------
template<int D, bool P>
__device__ void gat_body(int lb, const int* __restrict__ rp, const int* __restrict__ srcS,
                         const float* __restrict__ wS,
                         const float* __restrict__ xl, const float* __restrict__ xr,
                         const float* __restrict__ att,
                         const float* __restrict__ bias, float* __restrict__ out,
                         const int* __restrict__ pidx) {
    constexpr int T = D / 128;
    int node = (lb * 256 + threadIdx.x) >> 5;
    int lane = threadIdx.x & 31;
    if (node >= NN) return;
    int beg = rp[node], end = rp[node + 1];
    int nr = P ? pidx[node] : node;
    const float4* xrp = (const float4*)(xr + nr * D);
    const float4* ap = (const float4*)att;
    float4 xrv[T], av[T], acc[T];
#pragma unroll
    for (int t = 0; t < T; t++) {
        xrv[t] = xrp[lane + t * 32];
        av[t] = ap[lane + t * 32];
        acc[t] = make_float4(0.f, 0.f, 0.f, 0.f);
    }
    float den = 0.f;
    int k = beg;

#define LRELU4(vv, lg) { \
        float ex = vv.x + xrv[t].x; ex = ex > 0.f ? ex : 0.2f * ex; \
        float ey = vv.y + xrv[t].y; ey = ey > 0.f ? ey : 0.2f * ey; \
        float ez = vv.z + xrv[t].z; ez = ez > 0.f ? ez : 0.2f * ez; \
        float ew = vv.w + xrv[t].w; ew = ew > 0.f ? ew : 0.2f * ew; \
        lg += ex * av[t].x + ey * av[t].y + ez * av[t].z + ew * av[t].w; }

    if (T == 1) {
        // 4-edge ILP (D=128)
        for (; k + 3 < end; k += 4) {
            int s0 = srcS[k], s1 = srcS[k + 1], s2 = srcS[k + 2], s3 = srcS[k + 3];
            if (P) { s0 = pidx[s0]; s1 = pidx[s1]; s2 = pidx[s2]; s3 = pidx[s3]; }
            float4 v0, v1, v2, v3;
            float lg0 = 0.f, lg1 = 0.f, lg2 = 0.f, lg3 = 0.f;
            {
                const int t = 0;
                v0 = ((const float4*)(xl + s0 * D))[lane];
                v1 = ((const float4*)(xl + s1 * D))[lane];
                v2 = ((const float4*)(xl + s2 * D))[lane];
                v3 = ((const float4*)(xl + s3 * D))[lane];
                LRELU4(v0, lg0) LRELU4(v1, lg1) LRELU4(v2, lg2) LRELU4(v3, lg3)
            }
#pragma unroll
            for (int o = 16; o; o >>= 1) {
                lg0 += __shfl_xor_sync(0xffffffffu, lg0, o);
                lg1 += __shfl_xor_sync(0xffffffffu, lg1, o);
                lg2 += __shfl_xor_sync(0xffffffffu, lg2, o);
                lg3 += __shfl_xor_sync(0xffffffffu, lg3, o);
            }
            float w0 = __expf(lg0), w1 = __expf(lg1), w2 = __expf(lg2), w3 = __expf(lg3);
            den += (w0 + w1) + (w2 + w3);
            float a0 = w0 * wS[k], a1 = w1 * wS[k + 1], a2 = w2 * wS[k + 2], a3 = w3 * wS[k + 3];
            acc[0].x += a0 * v0.x + a1 * v1.x + a2 * v2.x + a3 * v3.x;
            acc[0].y += a0 * v0.y + a1 * v1.y + a2 * v2.y + a3 * v3.y;
            acc[0].z += a0 * v0.z + a1 * v1.z + a2 * v2.z + a3 * v3.z;
            acc[0].w += a0 * v0.w + a1 * v1.w + a2 * v2.w + a3 * v3.w;
        }
    }
    // 2-edge ILP
    for (; k + 1 < end; k += 2) {
        int s0 = srcS[k], s1 = srcS[k + 1];
        if (P) { s0 = pidx[s0]; s1 = pidx[s1]; }
        const float4* xp0 = (const float4*)(xl + s0 * D);
        const float4* xp1 = (const float4*)(xl + s1 * D);
        float4 v0[T], v1[T];
        float lg0 = 0.f, lg1 = 0.f;
#pragma unroll
        for (int t = 0; t < T; t++) {
            v0[t] = xp0[lane + t * 32];
            v1[t] = xp1[lane + t * 32];
            LRELU4(v0[t], lg0) LRELU4(v1[t], lg1)
        }
#pragma unroll
        for (int o = 16; o; o >>= 1) {
            lg0 += __shfl_xor_sync(0xffffffffu, lg0, o);
            lg1 += __shfl_xor_sync(0xffffffffu, lg1, o);
        }
        float w0 = __expf(lg0), w1 = __expf(lg1);
        den += w0 + w1;
        float a0 = w0 * wS[k], a1 = w1 * wS[k + 1];
#pragma unroll
        for (int t = 0; t < T; t++) {
            acc[t].x += a0 * v0[t].x + a1 * v1[t].x;
            acc[t].y += a0 * v0[t].y + a1 * v1[t].y;
            acc[t].z += a0 * v0[t].z + a1 * v1[t].z;
            acc[t].w += a0 * v0[t].w + a1 * v1[t].w;
        }
    }
    if (k < end) {
        int s = srcS[k];
        if (P) s = pidx[s];
        const float4* xp = (const float4*)(xl + s * D);
        float4 v[T];
        float lg = 0.f;
#pragma unroll
        for (int t = 0; t < T; t++) {
            v[t] = xp[lane + t * 32];
            LRELU4(v[t], lg)
        }
#pragma unroll
        for (int o = 16; o; o >>= 1) lg += __shfl_xor_sync(0xffffffffu, lg, o);
        float w = __expf(lg);
        den += w;
        float a = w * wS[k];
#pragma unroll
        for (int t = 0; t < T; t++) {
            acc[t].x += a * v[t].x; acc[t].y += a * v[t].y;
            acc[t].z += a * v[t].z; acc[t].w += a * v[t].w;
        }
    }
#undef LRELU4
    float inv = 1.f / (den + 1e-16f);
    float4* op = (float4*)(out + node * D);
    const float4* bp = (const float4*)bias;
#pragma unroll
    for (int t = 0; t < T; t++) {
        float4 b = bp[lane + t * 32];
        op[lane + t * 32] = make_float4(acc[t].x * inv + b.x, acc[t].y * inv + b.y,
                                        acc[t].z * inv + b.z, acc[t].w * inv + b.w);
    }
}

// 3 encoder GATs in one kernel
__global__ void __launch_bounds__(256) k_gat_enc(const float* att, const float* bias, float* hi) {
    int b = blockIdx.x;
    int y = b >> 10, lb = b & 1023;
    if (y == 0) gat_body<DL, false>(lb, g_rp_s, g_src_s, g_w_s, g_xl_e, g_xr_e, att, bias, hi, nullptr);
    else if (y == 1) gat_body<DL, false>(lb, g_rp_f, g_src_f, g_w_f, g_xl_p, g_xr_p, att, bias, g_g1, nullptr);
    else gat_body<DL, true>(lb, g_rp_s, g_src_s, g_w_s, g_xl_e, g_xr_e, att, bias, g_g2, g_perm);
}

// ------------------------- BN apply + ELU + L2 + bf16 -------------------------
__device__ void bnl2_body(int lb, const float* __restrict__ a0, const float* __restrict__ a1,
                          const float* __restrict__ a2,
                          const float* __restrict__ gamma, const float* __restrict__ beta) {
    int y = lb / 1024, xb = lb % 1024;
    const float* A = (y == 0) ? a0 : (y == 1 ? a1 : a2);
    __nv_bfloat16* B = (y == 0) ? g_q16 : (y == 1 ? g_p16 : g_n16);
    int gt = xb * 256 + threadIdx.x;
    int row = gt >> 5, lane = threadIdx.x & 31;
    if (row >= NN) return;
    float4 v = ((const float4*)(A + row * DL))[lane];
    float4 sm = ((const float4*)g_bns[y])[lane];
    float4 sq = ((const float4*)g_bnq[y])[lane];
    float4 ga = ((const float4*)gamma)[lane];
    float4 be = ((const float4*)beta)[lane];
    float mu, var, t;
#define BNE(comp) \
    mu = sm.comp * (1.f / NN); var = sq.comp * (1.f / NN) - mu * mu; \
    t = (v.comp - mu) * rsqrtf(var + 1e-5f) * ga.comp + be.comp; \
    v.comp = t > 0.f ? t : expm1f(t);
    BNE(x) BNE(y) BNE(z) BNE(w)
#undef BNE
    float s = v.x * v.x + v.y * v.y + v.z * v.z + v.w * v.w;
#pragma unroll
    for (int o = 16; o; o >>= 1) s += __shfl_xor_sync(0xffffffffu, s, o);
    float inv = 1.f / sqrtf(s);
    __nv_bfloat162* qp = (__nv_bfloat162*)(B + row * DL);
    qp[lane * 2]     = __floats2bfloat162_rn(v.x * inv, v.y * inv);
    qp[lane * 2 + 1] = __floats2bfloat162_rn(v.z * inv, v.w * inv);
}

// k_post: gat_dec(1024) | bnl2(3072)
__global__ void __launch_bounds__(256) k_post(const float* dec_att, const float* dec_b, float* h,
                                              const float* hiOut, const float* bn_g, const float* bn_b) {
    int b = blockIdx.x;
    if (b < 1024) gat_body<DI, false>(b, g_rp_s, g_src_s, g_w_s, g_xl_d, g_xr_d, dec_att, dec_b, h, nullptr);
    else bnl2_body(b - 1024, hiOut, g_g1, g_g2, bn_g, bn_b);
}

// ------------------------- InfoNCE: mma.sync + register exp epilogue + cp.async prefetch -------------------------
#define QS_W 136
#define NCE_SMEM ((64*QS_W + 2*128*QS_W) * 2)
__device__ __forceinline__ void mma16816(float* c, uint32_t a0, uint32_t a1, uint32_t a2, uint32_t a3,
                                         uint32_t b0, uint32_t b1) {
    asm volatile(
        "mma.sync.aligned.m16n8k16.row.col.f32.bf16.bf16.f32 "
        "{%0,%1,%2,%3}, {%4,%5,%6,%7}, {%8,%9}, {%0,%1,%2,%3};"
        : "+f"(c[0]), "+f"(c[1]), "+f"(c[2]), "+f"(c[3])
        : "r"(a0), "r"(a1), "r"(a2), "r"(a3), "r"(b0), "r"(b1));
}
__device__ __forceinline__ void cpa16(uint32_t dst, const void* src) {
    asm volatile("cp.async.cg.shared.global [%0], [%1], 16;" :: "r"(dst), "l"(src));
}

__global__ void k_nce() {
    extern __shared__ char smraw[];
    __nv_bfloat16* qs = (__nv_bfloat16*)smraw;                 // [64][136]
    __nv_bfloat16* ns0 = qs + 64 * QS_W;                       // [128][136]
    __nv_bfloat16* ns1 = ns0 + 128 * QS_W;                     // [128][136]
    __shared__ float pos2[64];
    __shared__ float rowS[64];
    __shared__ float blksum;
    int tid = threadIdx.x;
    int warp = tid >> 5, lane = tid & 31;
    int g = lane >> 2, tig = lane & 3;
    int r0 = blockIdx.x * 64;
    uint32_t ns0a = (uint32_t)__cvta_generic_to_shared(ns0);
    uint32_t ns1a = (uint32_t)__cvta_generic_to_shared(ns1);

    {
        const uint4* src = (const uint4*)(g_q16 + r0 * DL);
        uint4* dst4 = (uint4*)qs;
#pragma unroll
        for (int i = tid; i < 64 * 16; i += 256) {
            int row = i >> 4, c = i & 15;
            dst4[row * 17 + c] = src[i];
        }
    }
    // preload ns tile 0 via cp.async
    {
        const uint4* src = (const uint4*)g_n16;
#pragma unroll
        for (int i = tid; i < 128 * 16; i += 256) {
            int row = i >> 4, c = i & 15;
            cpa16(ns0a + (row * 17 + c) * 16, src + i);
        }
        asm volatile("cp.async.commit_group;");
    }
    if (tid < 64) rowS[tid] = 0.f;
    if (tid == 0) blksum = 0.f;
    __syncthreads();

    {
        int row = tid >> 2, part = tid & 3;
        float s = 0.f;
        const __nv_bfloat16* pr = g_p16 + (r0 + row) * DL;
        for (int k = part * 32; k < part * 32 + 32; k++)
            s += __bfloat162float(qs[row * QS_W + k]) * __bfloat162float(pr[k]);
        s += __shfl_down_sync(0xffffffffu, s, 1);
        s += __shfl_down_sync(0xffffffffu, s, 2);
        if (part == 0) pos2[row] = 2.f * s;
    }
    asm volatile("cp.async.wait_group 0;");
    __syncthreads();

    int wm = (warp & 3) * 16;
    int wn = (warp >> 2) * 64;
    int rA = wm + g;
    float s0 = 0.f, s1 = 0.f;

    for (int it = 0; it < 64; it++) {
        __nv_bfloat16* cur = (it & 1) ? ns1 : ns0;
        uint32_t nxta = (it & 1) ? ns0a : ns1a;
        if (it + 1 < 64) {
            const uint4* src = (const uint4*)(g_n16 + (it + 1) * 128 * DL);
#pragma unroll
            for (int i = tid; i < 128 * 16; i += 256) {
                int row = i >> 4, c = i & 15;
                cpa16(nxta + (row * 17 + c) * 16, src + i);
            }
            asm volatile("cp.async.commit_group;");
        }
        float c[8][4];
#pragma unroll
        for (int j = 0; j < 8; j++)
#pragma unroll
            for (int q = 0; q < 4; q++) c[j][q] = 0.f;
#pragma unroll
        for (int k0 = 0; k0 < 8; k0++) {
            int kb = k0 * 16;
            uint32_t a0 = *(const uint32_t*)&qs[rA * QS_W + kb + 2 * tig];
            uint32_t a1 = *(const uint32_t*)&qs[(rA + 8) * QS_W + kb + 2 * tig];
            uint32_t a2 = *(const uint32_t*)&qs[rA * QS_W + kb + 8 + 2 * tig];
            uint32_t a3 = *(const uint32_t*)&qs[(rA + 8) * QS_W + kb + 8 + 2 * tig];
#pragma unroll
            for (int j = 0; j < 8; j++) {
                int n = wn + j * 8 + g;
                uint32_t b0 = *(const uint32_t*)&cur[n * QS_W + kb + 2 * tig];
                uint32_t b1 = *(const uint32_t*)&cur[n * QS_W + kb + 8 + 2 * tig];
                mma16816(c[j], a0, a1, a2, a3, b0, b1);
            }
        }
#pragma unroll
        for (int j = 0; j < 8; j++) {
            s0 += __expf(2.f * c[j][0]) + __expf(2.f * c[j][1]);
            s1 += __expf(2.f * c[j][2]) + __expf(2.f * c[j][3]);
        }
        asm volatile("cp.async.wait_group 0;");
        __syncthreads();
    }
    s0 += __shfl_xor_sync(0xffffffffu, s0, 1);
    s0 += __shfl_xor_sync(0xffffffffu, s0, 2);
    s1 += __shfl_xor_sync(0xffffffffu, s1, 1);
    s1 += __shfl_xor_sync(0xffffffffu, s1, 2);
    if (tig == 0) {
        atomicAdd(&rowS[rA], s0);
        atomicAdd(&rowS[rA + 8], s1);
    }
    __syncthreads();
    if (tid < 64) {
        float S = rowS[tid];
        float p = pos2[tid];
        float l = logf(S + __expf(p)) - p;
        atomicAdd(&blksum, l);
    }
    __syncthreads();
    if (tid == 0) atomicAdd(&g_acc[1], blksum);
}

// ------------------------- rec loss + finalize + re-zero for next replay -------------------------
__global__ void __launch_bounds__(256) k_rec(const float* __restrict__ x, const float* __restrict__ h,
                                             float* __restrict__ loss) {
    float s = 0.f;
    for (int i = blockIdx.x * blockDim.x + threadIdx.x; i < NN * DI; i += gridDim.x * blockDim.x) {
        float d = x[i] - h[i];
        s += d * d;
    }
#pragma unroll
    for (int o = 16; o; o >>= 1) s += __shfl_down_sync(0xffffffffu, s, o);
    __shared__ float red[8];
    int lane = threadIdx.x & 31, wid = threadIdx.x >> 5;
    if (lane == 0) red[wid] = s;
    __syncthreads();
    int b = blockIdx.x;
    if (threadIdx.x < 32) {
        int idx = b * 32 + threadIdx.x;
        g_deg_s[idx] = 0; g_deg_f[idx] = 0;
        g_bh0[idx] = 0;   g_bh1[idx] = 0;
    }
    if (b < 3 && threadIdx.x >= 32 && threadIdx.x < 32 + DL) {
        g_bns[b][threadIdx.x - 32] = 0.f;
        g_bnq[b][threadIdx.x - 32] = 0.f;
    }
    __syncthreads();
    if (threadIdx.x == 0) {
        float t = 0.f;
        for (int i = 0; i < 8; i++) t += red[i];
        atomicAdd(&g_acc[0], t);
        __threadfence();
        unsigned old = atomicInc(&g_cnt, 255u);
        if (old == 255u) {
            __threadfence();
            loss[0] = g_acc[0] * (1.f / (float)(NN * DI)) + 0.2f * (g_acc[1] * (1.f / (float)NN));
            g_acc[0] = 0.f; g_acc[1] = 0.f;
        }
    }
}

// ------------------------- host orchestration (single stream) -------------------------
extern "C" void kernel_launch(void* const* d_in, const int* in_sizes, int n_in,
                              void* d_out, int out_size) {
    (void)in_sizes; (void)n_in; (void)out_size;
    const float* x       = (const float*)d_in[0];
    const int*   gsi     = (const int*)d_in[1];
    const int*   gfi     = (const int*)d_in[2];
    const float* w_h     = (const float*)d_in[3];
    const float* w_h_a   = (const float*)d_in[4];
    const float* enc_Wl  = (const float*)d_in[5];
    const float* enc_Wr  = (const float*)d_in[6];
    const float* enc_att = (const float*)d_in[7];
    const float* enc_b   = (const float*)d_in[8];
    const float* dec_Wl  = (const float*)d_in[9];
    const float* dec_Wr  = (const float*)d_in[10];
    const float* dec_att = (const float*)d_in[11];
    const float* dec_b   = (const float*)d_in[12];
    const float* bn_g    = (const float*)d_in[13];
    const float* bn_b    = (const float*)d_in[14];

    float* out  = (float*)d_out;
    float* hi   = out;
    float* h    = out + H_OFF;
    float* loss = out + LOSS_OFF;

    const int* s_src = gsi;
    const int* s_dst = gsi + EE;
    const int* f_src = gfi;
    const int* f_dst = gfi + EE;

    cudaFuncSetAttribute(k_nce, cudaFuncAttributeMaxDynamicSharedMemorySize, NCE_SMEM);
    cudaFuncSetAttribute(k_gemm3, cudaFuncAttributeMaxDynamicSharedMemorySize, GEMM_SMEM);

    void* p;
    cudaGetSymbolAddress(&p, g_Ah); __nv_bfloat16* Ah = (__nv_bfloat16*)p;
    cudaGetSymbolAddress(&p, g_Al); __nv_bfloat16* Al = (__nv_bfloat16*)p;
    cudaGetSymbolAddress(&p, g_xl_e); float* xle = (float*)p;
    cudaGetSymbolAddress(&p, g_xr_e); float* xre = (float*)p;
    cudaGetSymbolAddress(&p, g_xl_p); float* xlp = (float*)p;
    cudaGetSymbolAddress(&p, g_xr_p); float* xrp = (float*)p;
    cudaGetSymbolAddress(&p, g_xl_d); float* xld = (float*)p;
    cudaGetSymbolAddress(&p, g_xr_d); float* xrd = (float*)p;
    cudaGetSymbolAddress(&p, g_g1); float* gg1 = (float*)p;
    cudaGetSymbolAddress(&p, g_g2); float* gg2 = (float*)p;

    k_prep<<<4640, 256>>>(s_dst, f_dst, x, enc_Wl, enc_Wr);
    k_scan4<<<4, 1024>>>();
    k_fill2<<<2112, 256>>>(s_src, s_dst, w_h, f_src, f_dst, w_h_a);
    k_rank<<<64, 256>>>();

    k_gemm3<<<544, 256, GEMM_SMEM>>>(Ah, Al, DI, xle, xre, xlp, xrp, 7, 1);
    k_gat_enc<<<3072, 256>>>(enc_att, enc_b, hi);

    kCP_dec<<<1376, 256>>>(hi, dec_Wl, dec_Wr, gg1, gg2);
    k_gemm3<<<512, 256, GEMM_SMEM>>>(Ah, Al, DL, xld, xrd, xld, xrd, 8, 0);
    k_post<<<4096, 256>>>(dec_att, dec_b, h, hi, bn_g, bn_b);

    k_nce<<<128, 256, NCE_SMEM>>>();
    k_rec<<<256, 256>>>(x, h, loss);
}

// round 16
// speedup vs baseline: 1.1967x; 1.0010x over previous
#include <cuda_runtime.h>
#include <cuda_bf16.h>
#include <mma.h>
#include <stdint.h>
#include <math.h>

using namespace nvcuda;

#define NN 8192
#define EE 262144
#define DI 256
#define DL 128

#define H_OFF (NN*DL)
#define LOSS_OFF (NN*DL + NN*DI)

// ------------------------- scratch (__device__ globals; zero-initialized) -------------------------
__device__ float g_xl_e[NN*DL];
__device__ float g_xr_e[NN*DL];
__device__ float g_xl_p[NN*DL];
__device__ float g_xr_p[NN*DL];
__device__ float g_xl_d[NN*DI];
__device__ float g_xr_d[NN*DI];
__device__ float g_g1[NN*DL];
__device__ float g_g2[NN*DL];
__device__ __nv_bfloat16 g_q16[NN*DL];
__device__ __nv_bfloat16 g_p16[NN*DL];
__device__ __nv_bfloat16 g_n16[NN*DL];
__device__ int g_perm[NN];
__device__ unsigned g_bits0[NN];
__device__ unsigned g_bits1[NN];
__device__ float g_bns[3][DL];
__device__ float g_bnq[3][DL];
__device__ float g_acc[2];         // [0]=rec_sum [1]=ctr_sum
__device__ unsigned g_cnt;

// bucket-sort rank scratch
__device__ int g_bh0[NN];
__device__ int g_bh1[NN];
__device__ int g_bs0[NN+1];
__device__ int g_bs1[NN+1];
__device__ int g_bc0[NN];
__device__ int g_bc1[NN];
__device__ int g_si0[NN];
__device__ int g_si1[NN];
__device__ int g_r0[NN];
__device__ int g_r1[NN];

// bf16 split buffers
__device__ __nv_bfloat16 g_Ah[NN*DI];
__device__ __nv_bfloat16 g_Al[NN*DI];
__device__ __nv_bfloat16 g_Bh[DI*512];
__device__ __nv_bfloat16 g_Bl[DI*512];

// CSR scratch (per graph)
__device__ int g_deg_s[NN];
__device__ int g_deg_f[NN];
__device__ int g_cur_s[NN];
__device__ int g_cur_f[NN];
__device__ int g_rp_s[NN+1];
__device__ int g_src_s[EE];
__device__ float g_w_s[EE];
__device__ int g_rp_f[NN+1];
__device__ int g_src_f[EE];
__device__ float g_w_f[EE];

// ------------------------- threefry2x32-20 -------------------------
__device__ __forceinline__ void tfry(uint32_t k0, uint32_t k1, uint32_t x0, uint32_t x1,
                                     uint32_t* o0, uint32_t* o1) {
    uint32_t ks2 = k0 ^ k1 ^ 0x1BD11BDAu;
    x0 += k0; x1 += k1;
#define RR(r) { x0 += x1; x1 = (x1 << (r)) | (x1 >> (32 - (r))); x1 ^= x0; }
    RR(13) RR(15) RR(26) RR(6)  x0 += k1;  x1 += ks2 + 1u;
    RR(17) RR(29) RR(16) RR(24) x0 += ks2; x1 += k0 + 2u;
    RR(13) RR(15) RR(26) RR(6)  x0 += k0;  x1 += k1 + 3u;
    RR(17) RR(29) RR(16) RR(24) x0 += k1;  x1 += ks2 + 4u;
    RR(13) RR(15) RR(26) RR(6)  x0 += ks2; x1 += k0 + 5u;
#undef RR
    *o0 = x0; *o1 = x1;
}

__device__ __forceinline__ void all_keys(uint32_t* ks) {
    uint32_t a0, a1, b0, b1;
    tfry(0u, 42u, 0u, 2u, &a0, &a1);
    tfry(0u, 42u, 1u, 3u, &b0, &b1);
    uint32_t c0, c1, d0, d1;
    tfry(a0, b0, 0u, 2u, &c0, &c1);
    tfry(a0, b0, 1u, 3u, &d0, &d1);
    ks[0] = c1; ks[1] = d1;
    uint32_t e0, e1, f0, f1;
    tfry(c0, d0, 0u, 2u, &e0, &e1);
    tfry(c0, d0, 1u, 3u, &f0, &f1);
    ks[2] = e1; ks[3] = f1;
    ks[4] = a1; ks[5] = b1;
}

// ------------------------- cvt / pack bodies -------------------------
__device__ void cvt4_body(int lb, const float* __restrict__ src,
                          __nv_bfloat16* __restrict__ hi, __nv_bfloat16* __restrict__ lo, int n4) {
    int i = lb * 256 + threadIdx.x;
    if (i >= n4) return;
    float4 a = ((const float4*)src)[i];
    __nv_bfloat162 h0 = __floats2bfloat162_rn(a.x, a.y);
    __nv_bfloat162 h1 = __floats2bfloat162_rn(a.z, a.w);
    float lx = a.x - __bfloat162float(__low2bfloat16(h0));
    float ly = a.y - __bfloat162float(__high2bfloat16(h0));
    float lz = a.z - __bfloat162float(__low2bfloat16(h1));
    float lw = a.w - __bfloat162float(__high2bfloat16(h1));
    ((__nv_bfloat162*)hi)[i * 2] = h0;
    ((__nv_bfloat162*)hi)[i * 2 + 1] = h1;
    ((__nv_bfloat162*)lo)[i * 2] = __floats2bfloat162_rn(lx, ly);
    ((__nv_bfloat162*)lo)[i * 2 + 1] = __floats2bfloat162_rn(lz, lw);
}

__device__ __forceinline__ float keep_val(int k) {
    uint32_t ks[6];
    all_keys(ks);
    uint32_t lo, hi;
    int i = (k < 128) ? k : (k - 128);
    tfry(ks[4], ks[5], (uint32_t)i, (uint32_t)(i + 128), &lo, &hi);
    uint32_t u = (k < 128) ? lo : hi;
    float uf = __uint_as_float((u >> 9) | 0x3f800000u) - 1.0f;
    return (uf >= 0.3f) ? 1.f : 0.f;
}

// ------------------------- prep: hist(2048) | bits(32) | cvt_enc(2048) | packB_enc(512) -------------------------
__global__ void __launch_bounds__(256) k_prep(const int* __restrict__ s_dst, const int* __restrict__ f_dst,
                                              const float* __restrict__ x,
                                              const float* __restrict__ Wl, const float* __restrict__ Wr) {
    int b = blockIdx.x;
    if (b < 1024) {
        int e = b * 256 + threadIdx.x;
        if (e < EE) atomicAdd(&g_deg_s[s_dst[e]], 1);
        return;
    }
    if (b < 2048) {
        int e = (b - 1024) * 256 + threadIdx.x;
        if (e < EE) atomicAdd(&g_deg_f[f_dst[e]], 1);
        return;
    }
    if (b < 2080) {
        int bb = b - 2048;
        int which = (bb < 16) ? 0 : 1;
        int i = (which ? bb - 16 : bb) * 256 + threadIdx.x;
        if (i >= NN / 2) return;
        uint32_t ks[6];
        all_keys(ks);
        uint32_t lo, hi;
        tfry(ks[which * 2], ks[which * 2 + 1], (uint32_t)i, (uint32_t)(i + NN / 2), &lo, &hi);
        unsigned* bits = which ? g_bits1 : g_bits0;
        int* bh = which ? g_bh1 : g_bh0;
        bits[i] = lo; bits[i + NN / 2] = hi;
        atomicAdd(&bh[lo >> 19], 1);
        atomicAdd(&bh[hi >> 19], 1);
        return;
    }
    if (b < 4128) { cvt4_body(b - 2080, x, g_Ah, g_Al, NN * DI / 4); return; }
    int idx = (b - 4128) * 256 + threadIdx.x;
    if (idx >= DI * 512) return;
    int k = idx >> 9, c = idx & 511;
    float v;
    if (c < 128) v = Wl[k * 128 + c];
    else if (c < 256) v = Wr[k * 128 + c - 128];
    else if (c < 384) v = keep_val(k) * Wl[k * 128 + c - 256];
    else v = keep_val(k) * Wr[k * 128 + c - 384];
    __nv_bfloat16 h = __float2bfloat16_rn(v);
    g_Bh[idx] = h;
    g_Bl[idx] = __float2bfloat16_rn(v - __bfloat162float(h));
}

// ------------------------- scans -------------------------
__device__ void scan_body(const int* __restrict__ deg, int* __restrict__ rp, int* __restrict__ cur) {
    __shared__ int wsum[32];
    int tid = threadIdx.x;
    int lane = tid & 31, w = tid >> 5;
    int loc[8]; int s = 0;
#pragma unroll
    for (int i = 0; i < 8; i++) { loc[i] = deg[tid * 8 + i]; s += loc[i]; }
    int ss = s;
#pragma unroll
    for (int o = 1; o < 32; o <<= 1) { int v = __shfl_up_sync(0xffffffffu, ss, o); if (lane >= o) ss += v; }
    if (lane == 31) wsum[w] = ss;
    __syncthreads();
    if (w == 0) {
        int v = wsum[lane];
#pragma unroll
        for (int o = 1; o < 32; o <<= 1) { int u = __shfl_up_sync(0xffffffffu, v, o); if (lane >= o) v += u; }
        wsum[lane] = v;
    }
    __syncthreads();
    int base = ss - s + (w > 0 ? wsum[w - 1] : 0);
#pragma unroll
    for (int i = 0; i < 8; i++) { rp[tid * 8 + i] = base; cur[tid * 8 + i] = base; base += loc[i]; }
    if (tid == 1023) rp[NN] = base;
}

__global__ void __launch_bounds__(1024) k_scan4() {
    int b = blockIdx.x;
    if (b == 0) scan_body(g_deg_s, g_rp_s, g_cur_s);
    else if (b == 1) scan_body(g_deg_f, g_rp_f, g_cur_f);
    else if (b == 2) scan_body(g_bh0, g_bs0, g_bc0);
    else scan_body(g_bh1, g_bs1, g_bc1);
}

// edge fill (2048) + bucket scatter (64)
__global__ void __launch_bounds__(256) k_fill2(const int* __restrict__ s_src, const int* __restrict__ s_dst,
                                               const float* __restrict__ w_h,
                                               const int* __restrict__ f_src, const int* __restrict__ f_dst,
                                               const float* __restrict__ w_h_a) {
    int b = blockIdx.x;
    if (b < 1024) {
        int e = b * 256 + threadIdx.x;
        if (e >= EE) return;
        int d = s_dst[e];
        int pos = atomicAdd(&g_cur_s[d], 1);
        g_src_s[pos] = s_src[e];
        g_w_s[pos] = w_h[e];
    } else if (b < 2048) {
        int e = (b - 1024) * 256 + threadIdx.x;
        if (e >= EE) return;
        int d = f_dst[e];
        int pos = atomicAdd(&g_cur_f[d], 1);
        g_src_f[pos] = f_src[e];
        g_w_f[pos] = w_h_a[e];
    } else if (b < 2080) {
        int i = (b - 2048) * 256 + threadIdx.x;
        if (i >= NN) return;
        int pos = atomicAdd(&g_bc0[g_bits0[i] >> 19], 1);
        g_si0[pos] = i;
    } else {
        int i = (b - 2080) * 256 + threadIdx.x;
        if (i >= NN) return;
        int pos = atomicAdd(&g_bc1[g_bits1[i] >> 19], 1);
        g_si1[pos] = i;
    }
}

// per-element rank via bucket scan (both keys)
__global__ void __launch_bounds__(256) k_rank() {
    int b = blockIdx.x;
    int which = (b < 32) ? 0 : 1;
    int p = (which ? b - 32 : b) * 256 + threadIdx.x;
    if (p >= NN) return;
    const unsigned* bits = which ? g_bits1 : g_bits0;
    const int* si = which ? g_si1 : g_si0;
    const int* bs = which ? g_bs1 : g_bs0;
    int* r = which ? g_r1 : g_r0;
    int i = si[p];
    unsigned bi = bits[i];
    unsigned long long ki = (((unsigned long long)bi) << 13) | (unsigned)i;
    int bkt = bi >> 19;
    int beg = bs[bkt], end = bs[bkt + 1];
    int cnt = 0;
    for (int q = beg; q < end; q++) {
        int j = si[q];
        unsigned long long kj = (((unsigned long long)bits[j]) << 13) | (unsigned)j;
        cnt += (kj < ki);
    }
    r[i] = beg + cnt;
}

// bnstats body
__device__ void bnstats_body(int lb, const float* __restrict__ a0, const float* __restrict__ a1,
                             const float* __restrict__ a2) {
    int y = lb / 32, xb = lb % 32;
    const float* A = (y == 0) ? a0 : (y == 1 ? a1 : a2);
    int c = threadIdx.x % DL;
    int part = threadIdx.x / DL;
    int rbase = xb * 256 + part * 128;
    float s = 0.f, q = 0.f;
    for (int r = 0; r < 128; r++) {
        float v = A[(rbase + r) * DL + c];
        s += v; q += v * v;
    }
    atomicAdd(&g_bns[y][c], s);
    atomicAdd(&g_bnq[y][c], q);
}

// kCP_dec: cvt_dec(1024) | packB_dec(256) | bnstats(96)
__global__ void __launch_bounds__(256) kCP_dec(const float* __restrict__ hiOut,
                                               const float* __restrict__ Wl, const float* __restrict__ Wr,
                                               const float* __restrict__ g1, const float* __restrict__ g2) {
    int b = blockIdx.x;
    if (b < 1024) { cvt4_body(b, hiOut, g_Ah, g_Al, NN * DL / 4); return; }
    if (b < 1280) {
        int idx = (b - 1024) * 256 + threadIdx.x;
        if (idx >= DL * 512) return;
        int k = idx >> 9, c = idx & 511;
        float v = (c < 256) ? Wl[k * 256 + c] : Wr[k * 256 + c - 256];
        __nv_bfloat16 h = __float2bfloat16_rn(v);
        g_Bh[idx] = h;
        g_Bl[idx] = __float2bfloat16_rn(v - __bfloat162float(h));
        return;
    }
    bnstats_body(b - 1280, hiOut, g1, g2);
}

// ------------------------- bf16x3 GEMM, double-buffered k-panels (+ permc rider) -------------------------
#define GEMM_BUF 13824
#define GEMM_SMEM (GEMM_BUF * 2 * 2)
__global__ void __launch_bounds__(256) k_gemm3(const __nv_bfloat16* __restrict__ Ah,
                                               const __nv_bfloat16* __restrict__ Al, int K,
                                               float* o0, float* o1, float* o2, float* o3, int lgw,
                                               int with_permc) {
    int bx = blockIdx.x;
    if (with_permc && bx >= 512) {
        int j = (bx - 512) * 256 + threadIdx.x;
        if (j < NN) g_perm[g_r1[g_r0[j]]] = j;
        return;
    }
    extern __shared__ __nv_bfloat16 gsm[];
    int tid = threadIdx.x;
    int warp = tid >> 5;
    int wm = warp >> 2, wn = warp & 3;
    int row0 = (bx >> 2) * 64, col0 = (bx & 3) * 128;
    wmma::fragment<wmma::accumulator, 16, 16, 16, float> c[2][2];
#pragma unroll
    for (int i = 0; i < 2; i++)
#pragma unroll
        for (int j = 0; j < 2; j++) wmma::fill_fragment(c[i][j], 0.f);
    int r = tid >> 2, q = tid & 3;
    int bk0 = tid >> 4, bq0 = tid & 15;
    int bk1 = (tid + 256) >> 4, bq1 = (tid + 256) & 15;
    int np = K / 32;

    {
        __nv_bfloat16* buf = gsm;
        *(uint4*)&buf[r * 40 + q * 8]            = *(const uint4*)&Ah[(row0 + r) * K + q * 8];
        *(uint4*)&buf[2560 + r * 40 + q * 8]     = *(const uint4*)&Al[(row0 + r) * K + q * 8];
        *(uint4*)&buf[5120 + bk0 * 136 + bq0 * 8] = *(const uint4*)&g_Bh[bk0 * 512 + col0 + bq0 * 8];
        *(uint4*)&buf[5120 + bk1 * 136 + bq1 * 8] = *(const uint4*)&g_Bh[bk1 * 512 + col0 + bq1 * 8];
        *(uint4*)&buf[9472 + bk0 * 136 + bq0 * 8] = *(const uint4*)&g_Bl[bk0 * 512 + col0 + bq0 * 8];
        *(uint4*)&buf[9472 + bk1 * 136 + bq1 * 8] = *(const uint4*)&g_Bl[bk1 * 512 + col0 + bq1 * 8];
    }
    __syncthreads();

    for (int kp = 0; kp < np; kp++) {
        __nv_bfloat16* cur = gsm + (kp & 1) * GEMM_BUF;
        __nv_bfloat16* nxt = gsm + ((kp + 1) & 1) * GEMM_BUF;
        uint4 rAh, rAl, rBh0, rBh1, rBl0, rBl1;
        bool pf = (kp + 1 < np);
        if (pf) {
            int kn = (kp + 1) * 32;
            rAh  = *(const uint4*)&Ah[(row0 + r) * K + kn + q * 8];
            rAl  = *(const uint4*)&Al[(row0 + r) * K + kn + q * 8];
            rBh0 = *(const uint4*)&g_Bh[(kn + bk0) * 512 + col0 + bq0 * 8];
            rBh1 = *(const uint4*)&g_Bh[(kn + bk1) * 512 + col0 + bq1 * 8];
            rBl0 = *(const uint4*)&g_Bl[(kn + bk0) * 512 + col0 + bq0 * 8];
            rBl1 = *(const uint4*)&g_Bl[(kn + bk1) * 512 + col0 + bq1 * 8];
        }
#pragma unroll
        for (int ks = 0; ks < 32; ks += 16) {
            wmma::fragment<wmma::matrix_a, 16, 16, 16, __nv_bfloat16, wmma::row_major> ah[2], al[2];
            wmma::fragment<wmma::matrix_b, 16, 16, 16, __nv_bfloat16, wmma::row_major> bh[2], bl[2];
#pragma unroll
            for (int i = 0; i < 2; i++) {
                wmma::load_matrix_sync(ah[i], &cur[(wm * 32 + i * 16) * 40 + ks], 40);
                wmma::load_matrix_sync(al[i], &cur[2560 + (wm * 32 + i * 16) * 40 + ks], 40);
            }
#pragma unroll
            for (int j = 0; j < 2; j++) {
                wmma::load_matrix_sync(bh[j], &cur[5120 + ks * 136 + wn * 32 + j * 16], 136);
                wmma::load_matrix_sync(bl[j], &cur[9472 + ks * 136 + wn * 32 + j * 16], 136);
            }
#pragma unroll
            for (int i = 0; i < 2; i++)
#pragma unroll
                for (int j = 0; j < 2; j++) {
                    wmma::mma_sync(c[i][j], ah[i], bh[j], c[i][j]);
                    wmma::mma_sync(c[i][j], ah[i], bl[j], c[i][j]);
                    wmma::mma_sync(c[i][j], al[i], bh[j], c[i][j]);
                }
        }
        if (pf) {
            *(uint4*)&nxt[r * 40 + q * 8]             = rAh;
            *(uint4*)&nxt[2560 + r * 40 + q * 8]      = rAl;
            *(uint4*)&nxt[5120 + bk0 * 136 + bq0 * 8] = rBh0;
            *(uint4*)&nxt[5120 + bk1 * 136 + bq1 * 8] = rBh1;
            *(uint4*)&nxt[9472 + bk0 * 136 + bq0 * 8] = rBl0;
            *(uint4*)&nxt[9472 + bk1 * 136 + bq1 * 8] = rBl1;
        }
        __syncthreads();
    }
    float* ob[4] = {o0, o1, o2, o3};
    int W = 1 << lgw, msk = W - 1;
#pragma unroll
    for (int i = 0; i < 2; i++)
#pragma unroll
        for (int j = 0; j < 2; j++) {
            int colg = col0 + wn * 32 + j * 16;
            float* dst = ob[colg >> lgw] + (size_t)(row0 + wm * 32 + i * 16) * W + (colg & msk);
            wmma::store_matrix_sync(dst, c[i][j], W, wmma::mem_row_major);
        }
}

// ------------------------- fused single-pass GAT -------------------------
// D=128: 4-edge ILP, rows kept in regs. D=256: 4-edge ILP with L1 reload for accumulate.
template<int D, bool P>
__device__ void gat_body(int lb, const int* __restrict__ rp, const int* __restrict__ srcS,
                         const float* __restrict__ wS,
                         const float* __restrict__ xl, const float* __restrict__ xr,
                         const float* __restrict__ att,
                         const float* __restrict__ bias, float* __restrict__ out,
                         const int* __restrict__ pidx) {
    constexpr int T = D / 128;
    int node = (lb * 256 + threadIdx.x) >> 5;
    int lane = threadIdx.x & 31;
    if (node >= NN) return;
    int beg = rp[node], end = rp[node + 1];
    int nr = P ? pidx[node] : node;
    const float4* xrp = (const float4*)(xr + nr * D);
    const float4* ap = (const float4*)att;
    float4 xrv[T], av[T], acc[T];
#pragma unroll
    for (int t = 0; t < T; t++) {
        xrv[t] = xrp[lane + t * 32];
        av[t] = ap[lane + t * 32];
        acc[t] = make_float4(0.f, 0.f, 0.f, 0.f);
    }
    float den = 0.f;
    int k = beg;

#define LRELU4(vv, lg) { \
        float ex = vv.x + xrv[t].x; ex = ex > 0.f ? ex : 0.2f * ex; \
        float ey = vv.y + xrv[t].y; ey = ey > 0.f ? ey : 0.2f * ey; \
        float ez = vv.z + xrv[t].z; ez = ez > 0.f ? ez : 0.2f * ez; \
        float ew = vv.w + xrv[t].w; ew = ew > 0.f ? ew : 0.2f * ew; \
        lg += ex * av[t].x + ey * av[t].y + ez * av[t].z + ew * av[t].w; }

    if (T == 1) {
        // 4-edge ILP (D=128), rows kept live
        for (; k + 3 < end; k += 4) {
            int s0 = srcS[k], s1 = srcS[k + 1], s2 = srcS[k + 2], s3 = srcS[k + 3];
            if (P) { s0 = pidx[s0]; s1 = pidx[s1]; s2 = pidx[s2]; s3 = pidx[s3]; }
            float4 v0, v1, v2, v3;
            float lg0 = 0.f, lg1 = 0.f, lg2 = 0.f, lg3 = 0.f;
            {
                const int t = 0;
                v0 = ((const float4*)(xl + s0 * D))[lane];
                v1 = ((const float4*)(xl + s1 * D))[lane];
                v2 = ((const float4*)(xl + s2 * D))[lane];
                v3 = ((const float4*)(xl + s3 * D))[lane];
                LRELU4(v0, lg0) LRELU4(v1, lg1) LRELU4(v2, lg2) LRELU4(v3, lg3)
            }
#pragma unroll
            for (int o = 16; o; o >>= 1) {
                lg0 += __shfl_xor_sync(0xffffffffu, lg0, o);
                lg1 += __shfl_xor_sync(0xffffffffu, lg1, o);
                lg2 += __shfl_xor_sync(0xffffffffu, lg2, o);
                lg3 += __shfl_xor_sync(0xffffffffu, lg3, o);
            }
            float w0 = __expf(lg0), w1 = __expf(lg1), w2 = __expf(lg2), w3 = __expf(lg3);
            den += (w0 + w1) + (w2 + w3);
            float a0 = w0 * wS[k], a1 = w1 * wS[k + 1], a2 = w2 * wS[k + 2], a3 = w3 * wS[k + 3];
            acc[0].x += a0 * v0.x + a1 * v1.x + a2 * v2.x + a3 * v3.x;
            acc[0].y += a0 * v0.y + a1 * v1.y + a2 * v2.y + a3 * v3.y;
            acc[0].z += a0 * v0.z + a1 * v1.z + a2 * v2.z + a3 * v3.z;
            acc[0].w += a0 * v0.w + a1 * v1.w + a2 * v2.w + a3 * v3.w;
        }
    } else {
        // 4-edge ILP (D=256): logit phase discards rows; accumulate phase reloads (L1 hit)
        for (; k + 3 < end; k += 4) {
            int s0 = srcS[k], s1 = srcS[k + 1], s2 = srcS[k + 2], s3 = srcS[k + 3];
            if (P) { s0 = pidx[s0]; s1 = pidx[s1]; s2 = pidx[s2]; s3 = pidx[s3]; }
            const float4* xp0 = (const float4*)(xl + s0 * D);
            const float4* xp1 = (const float4*)(xl + s1 * D);
            const float4* xp2 = (const float4*)(xl + s2 * D);
            const float4* xp3 = (const float4*)(xl + s3 * D);
            float lg0 = 0.f, lg1 = 0.f, lg2 = 0.f, lg3 = 0.f;
#pragma unroll
            for (int t = 0; t < T; t++) {
                float4 u0 = xp0[lane + t * 32];
                float4 u1 = xp1[lane + t * 32];
                float4 u2 = xp2[lane + t * 32];
                float4 u3 = xp3[lane + t * 32];
                LRELU4(u0, lg0) LRELU4(u1, lg1) LRELU4(u2, lg2) LRELU4(u3, lg3)
            }
#pragma unroll
            for (int o = 16; o; o >>= 1) {
                lg0 += __shfl_xor_sync(0xffffffffu, lg0, o);
                lg1 += __shfl_xor_sync(0xffffffffu, lg1, o);
                lg2 += __shfl_xor_sync(0xffffffffu, lg2, o);
                lg3 += __shfl_xor_sync(0xffffffffu, lg3, o);
            }
            float w0 = __expf(lg0), w1 = __expf(lg1), w2 = __expf(lg2), w3 = __expf(lg3);
            den += (w0 + w1) + (w2 + w3);
            float a0 = w0 * wS[k], a1 = w1 * wS[k + 1], a2 = w2 * wS[k + 2], a3 = w3 * wS[k + 3];
#pragma unroll
            for (int t = 0; t < T; t++) {
                float4 u0 = xp0[lane + t * 32];
                float4 u1 = xp1[lane + t * 32];
                float4 u2 = xp2[lane + t * 32];
                float4 u3 = xp3[lane + t * 32];
                acc[t].x += a0 * u0.x + a1 * u1.x + a2 * u2.x + a3 * u3.x;
                acc[t].y += a0 * u0.y + a1 * u1.y + a2 * u2.y + a3 * u3.y;
                acc[t].z += a0 * u0.z + a1 * u1.z + a2 * u2.z + a3 * u3.z;
                acc[t].w += a0 * u0.w + a1 * u1.w + a2 * u2.w + a3 * u3.w;
            }
        }
    }
    // remainder (sequential)
    for (; k < end; k++) {
        int s = srcS[k];
        if (P) s = pidx[s];
        const float4* xp = (const float4*)(xl + s * D);
        float4 v[T];
        float lg = 0.f;
#pragma unroll
        for (int t = 0; t < T; t++) {
            v[t] = xp[lane + t * 32];
            LRELU4(v[t], lg)
        }
#pragma unroll
        for (int o = 16; o; o >>= 1) lg += __shfl_xor_sync(0xffffffffu, lg, o);
        float w = __expf(lg);
        den += w;
        float a = w * wS[k];
#pragma unroll
        for (int t = 0; t < T; t++) {
            acc[t].x += a * v[t].x; acc[t].y += a * v[t].y;
            acc[t].z += a * v[t].z; acc[t].w += a * v[t].w;
        }
    }
#undef LRELU4
    float inv = 1.f / (den + 1e-16f);
    float4* op = (float4*)(out + node * D);
    const float4* bp = (const float4*)bias;
#pragma unroll
    for (int t = 0; t < T; t++) {
        float4 b = bp[lane + t * 32];
        op[lane + t * 32] = make_float4(acc[t].x * inv + b.x, acc[t].y * inv + b.y,
                                        acc[t].z * inv + b.z, acc[t].w * inv + b.w);
    }
}

// 3 encoder GATs in one kernel
__global__ void __launch_bounds__(256) k_gat_enc(const float* att, const float* bias, float* hi) {
    int b = blockIdx.x;
    int y = b >> 10, lb = b & 1023;
    if (y == 0) gat_body<DL, false>(lb, g_rp_s, g_src_s, g_w_s, g_xl_e, g_xr_e, att, bias, hi, nullptr);
    else if (y == 1) gat_body<DL, false>(lb, g_rp_f, g_src_f, g_w_f, g_xl_p, g_xr_p, att, bias, g_g1, nullptr);
    else gat_body<DL, true>(lb, g_rp_s, g_src_s, g_w_s, g_xl_e, g_xr_e, att, bias, g_g2, g_perm);
}

// ------------------------- BN apply + ELU + L2 + bf16 -------------------------
__device__ void bnl2_body(int lb, const float* __restrict__ a0, const float* __restrict__ a1,
                          const float* __restrict__ a2,
                          const float* __restrict__ gamma, const float* __restrict__ beta) {
    int y = lb / 1024, xb = lb % 1024;
    const float* A = (y == 0) ? a0 : (y == 1 ? a1 : a2);
    __nv_bfloat16* B = (y == 0) ? g_q16 : (y == 1 ? g_p16 : g_n16);
    int gt = xb * 256 + threadIdx.x;
    int row = gt >> 5, lane = threadIdx.x & 31;
    if (row >= NN) return;
    float4 v = ((const float4*)(A + row * DL))[lane];
    float4 sm = ((const float4*)g_bns[y])[lane];
    float4 sq = ((const float4*)g_bnq[y])[lane];
    float4 ga = ((const float4*)gamma)[lane];
    float4 be = ((const float4*)beta)[lane];
    float mu, var, t;
#define BNE(comp) \
    mu = sm.comp * (1.f / NN); var = sq.comp * (1.f / NN) - mu * mu; \
    t = (v.comp - mu) * rsqrtf(var + 1e-5f) * ga.comp + be.comp; \
    v.comp = t > 0.f ? t : expm1f(t);
    BNE(x) BNE(y) BNE(z) BNE(w)
#undef BNE
    float s = v.x * v.x + v.y * v.y + v.z * v.z + v.w * v.w;
#pragma unroll
    for (int o = 16; o; o >>= 1) s += __shfl_xor_sync(0xffffffffu, s, o);
    float inv = 1.f / sqrtf(s);
    __nv_bfloat162* qp = (__nv_bfloat162*)(B + row * DL);
    qp[lane * 2]     = __floats2bfloat162_rn(v.x * inv, v.y * inv);
    qp[lane * 2 + 1] = __floats2bfloat162_rn(v.z * inv, v.w * inv);
}

// k_post: gat_dec(1024) | bnl2(3072)
__global__ void __launch_bounds__(256) k_post(const float* dec_att, const float* dec_b, float* h,
                                              const float* hiOut, const float* bn_g, const float* bn_b) {
    int b = blockIdx.x;
    if (b < 1024) gat_body<DI, false>(b, g_rp_s, g_src_s, g_w_s, g_xl_d, g_xr_d, dec_att, dec_b, h, nullptr);
    else bnl2_body(b - 1024, hiOut, g_g1, g_g2, bn_g, bn_b);
}

// ------------------------- InfoNCE: mma.sync + register exp epilogue + cp.async prefetch -------------------------
#define QS_W 136
#define NCE_SMEM ((64*QS_W + 2*128*QS_W) * 2)
__device__ __forceinline__ void mma16816(float* c, uint32_t a0, uint32_t a1, uint32_t a2, uint32_t a3,
                                         uint32_t b0, uint32_t b1) {
    asm volatile(
        "mma.sync.aligned.m16n8k16.row.col.f32.bf16.bf16.f32 "
        "{%0,%1,%2,%3}, {%4,%5,%6,%7}, {%8,%9}, {%0,%1,%2,%3};"
        : "+f"(c[0]), "+f"(c[1]), "+f"(c[2]), "+f"(c[3])
        : "r"(a0), "r"(a1), "r"(a2), "r"(a3), "r"(b0), "r"(b1));
}
__device__ __forceinline__ void cpa16(uint32_t dst, const void* src) {
    asm volatile("cp.async.cg.shared.global [%0], [%1], 16;" :: "r"(dst), "l"(src));
}

__global__ void k_nce() {
    extern __shared__ char smraw[];
    __nv_bfloat16* qs = (__nv_bfloat16*)smraw;                 // [64][136]
    __nv_bfloat16* ns0 = qs + 64 * QS_W;                       // [128][136]
    __nv_bfloat16* ns1 = ns0 + 128 * QS_W;                     // [128][136]
    __shared__ float pos2[64];
    __shared__ float rowS[64];
    __shared__ float blksum;
    int tid = threadIdx.x;
    int warp = tid >> 5, lane = tid & 31;
    int g = lane >> 2, tig = lane & 3;
    int r0 = blockIdx.x * 64;
    uint32_t ns0a = (uint32_t)__cvta_generic_to_shared(ns0);
    uint32_t ns1a = (uint32_t)__cvta_generic_to_shared(ns1);

    {
        const uint4* src = (const uint4*)(g_q16 + r0 * DL);
        uint4* dst4 = (uint4*)qs;
#pragma unroll
        for (int i = tid; i < 64 * 16; i += 256) {
            int row = i >> 4, c = i & 15;
            dst4[row * 17 + c] = src[i];
        }
    }
    {
        const uint4* src = (const uint4*)g_n16;
#pragma unroll
        for (int i = tid; i < 128 * 16; i += 256) {
            int row = i >> 4, c = i & 15;
            cpa16(ns0a + (row * 17 + c) * 16, src + i);
        }
        asm volatile("cp.async.commit_group;");
    }
    if (tid < 64) rowS[tid] = 0.f;
    if (tid == 0) blksum = 0.f;
    __syncthreads();

    {
        int row = tid >> 2, part = tid & 3;
        float s = 0.f;
        const __nv_bfloat16* pr = g_p16 + (r0 + row) * DL;
        for (int k = part * 32; k < part * 32 + 32; k++)
            s += __bfloat162float(qs[row * QS_W + k]) * __bfloat162float(pr[k]);
        s += __shfl_down_sync(0xffffffffu, s, 1);
        s += __shfl_down_sync(0xffffffffu, s, 2);
        if (part == 0) pos2[row] = 2.f * s;
    }
    asm volatile("cp.async.wait_group 0;");
    __syncthreads();

    int wm = (warp & 3) * 16;
    int wn = (warp >> 2) * 64;
    int rA = wm + g;
    float s0 = 0.f, s1 = 0.f;

    for (int it = 0; it < 64; it++) {
        __nv_bfloat16* cur = (it & 1) ? ns1 : ns0;
        uint32_t nxta = (it & 1) ? ns0a : ns1a;
        if (it + 1 < 64) {
            const uint4* src = (const uint4*)(g_n16 + (it + 1) * 128 * DL);
#pragma unroll
            for (int i = tid; i < 128 * 16; i += 256) {
                int row = i >> 4, c = i & 15;
                cpa16(nxta + (row * 17 + c) * 16, src + i);
            }
            asm volatile("cp.async.commit_group;");
        }
        float c[8][4];
#pragma unroll
        for (int j = 0; j < 8; j++)
#pragma unroll
            for (int q = 0; q < 4; q++) c[j][q] = 0.f;
#pragma unroll
        for (int k0 = 0; k0 < 8; k0++) {
            int kb = k0 * 16;
            uint32_t a0 = *(const uint32_t*)&qs[rA * QS_W + kb + 2 * tig];
            uint32_t a1 = *(const uint32_t*)&qs[(rA + 8) * QS_W + kb + 2 * tig];
            uint32_t a2 = *(const uint32_t*)&qs[rA * QS_W + kb + 8 + 2 * tig];
            uint32_t a3 = *(const uint32_t*)&qs[(rA + 8) * QS_W + kb + 8 + 2 * tig];
#pragma unroll
            for (int j = 0; j < 8; j++) {
                int n = wn + j * 8 + g;
                uint32_t b0 = *(const uint32_t*)&cur[n * QS_W + kb + 2 * tig];
                uint32_t b1 = *(const uint32_t*)&cur[n * QS_W + kb + 8 + 2 * tig];
                mma16816(c[j], a0, a1, a2, a3, b0, b1);
            }
        }
#pragma unroll
        for (int j = 0; j < 8; j++) {
            s0 += __expf(2.f * c[j][0]) + __expf(2.f * c[j][1]);
            s1 += __expf(2.f * c[j][2]) + __expf(2.f * c[j][3]);
        }
        asm volatile("cp.async.wait_group 0;");
        __syncthreads();
    }
    s0 += __shfl_xor_sync(0xffffffffu, s0, 1);
    s0 += __shfl_xor_sync(0xffffffffu, s0, 2);
    s1 += __shfl_xor_sync(0xffffffffu, s1, 1);
    s1 += __shfl_xor_sync(0xffffffffu, s1, 2);
    if (tig == 0) {
        atomicAdd(&rowS[rA], s0);
        atomicAdd(&rowS[rA + 8], s1);
    }
    __syncthreads();
    if (tid < 64) {
        float S = rowS[tid];
        float p = pos2[tid];
        float l = logf(S + __expf(p)) - p;
        atomicAdd(&blksum, l);
    }
    __syncthreads();
    if (tid == 0) atomicAdd(&g_acc[1], blksum);
}

// ------------------------- rec loss + finalize + re-zero for next replay -------------------------
__global__ void __launch_bounds__(256) k_rec(const float* __restrict__ x, const float* __restrict__ h,
                                             float* __restrict__ loss) {
    float s = 0.f;
    for (int i = blockIdx.x * blockDim.x + threadIdx.x; i < NN * DI; i += gridDim.x * blockDim.x) {
        float d = x[i] - h[i];
        s += d * d;
    }
#pragma unroll
    for (int o = 16; o; o >>= 1) s += __shfl_down_sync(0xffffffffu, s, o);
    __shared__ float red[8];
    int lane = threadIdx.x & 31, wid = threadIdx.x >> 5;
    if (lane == 0) red[wid] = s;
    __syncthreads();
    int b = blockIdx.x;
    if (threadIdx.x < 32) {
        int idx = b * 32 + threadIdx.x;
        g_deg_s[idx] = 0; g_deg_f[idx] = 0;
        g_bh0[idx] = 0;   g_bh1[idx] = 0;
    }
    if (b < 3 && threadIdx.x >= 32 && threadIdx.x < 32 + DL) {
        g_bns[b][threadIdx.x - 32] = 0.f;
        g_bnq[b][threadIdx.x - 32] = 0.f;
    }
    __syncthreads();
    if (threadIdx.x == 0) {
        float t = 0.f;
        for (int i = 0; i < 8; i++) t += red[i];
        atomicAdd(&g_acc[0], t);
        __threadfence();
        unsigned old = atomicInc(&g_cnt, 255u);
        if (old == 255u) {
            __threadfence();
            loss[0] = g_acc[0] * (1.f / (float)(NN * DI)) + 0.2f * (g_acc[1] * (1.f / (float)NN));
            g_acc[0] = 0.f; g_acc[1] = 0.f;
        }
    }
}

// ------------------------- host orchestration (single stream) -------------------------
extern "C" void kernel_launch(void* const* d_in, const int* in_sizes, int n_in,
                              void* d_out, int out_size) {
    (void)in_sizes; (void)n_in; (void)out_size;
    const float* x       = (const float*)d_in[0];
    const int*   gsi     = (const int*)d_in[1];
    const int*   gfi     = (const int*)d_in[2];
    const float* w_h     = (const float*)d_in[3];
    const float* w_h_a   = (const float*)d_in[4];
    const float* enc_Wl  = (const float*)d_in[5];
    const float* enc_Wr  = (const float*)d_in[6];
    const float* enc_att = (const float*)d_in[7];
    const float* enc_b   = (const float*)d_in[8];
    const float* dec_Wl  = (const float*)d_in[9];
    const float* dec_Wr  = (const float*)d_in[10];
    const float* dec_att = (const float*)d_in[11];
    const float* dec_b   = (const float*)d_in[12];
    const float* bn_g    = (const float*)d_in[13];
    const float* bn_b    = (const float*)d_in[14];

    float* out  = (float*)d_out;
    float* hi   = out;
    float* h    = out + H_OFF;
    float* loss = out + LOSS_OFF;

    const int* s_src = gsi;
    const int* s_dst = gsi + EE;
    const int* f_src = gfi;
    const int* f_dst = gfi + EE;

    cudaFuncSetAttribute(k_nce, cudaFuncAttributeMaxDynamicSharedMemorySize, NCE_SMEM);
    cudaFuncSetAttribute(k_gemm3, cudaFuncAttributeMaxDynamicSharedMemorySize, GEMM_SMEM);

    void* p;
    cudaGetSymbolAddress(&p, g_Ah); __nv_bfloat16* Ah = (__nv_bfloat16*)p;
    cudaGetSymbolAddress(&p, g_Al); __nv_bfloat16* Al = (__nv_bfloat16*)p;
    cudaGetSymbolAddress(&p, g_xl_e); float* xle = (float*)p;
    cudaGetSymbolAddress(&p, g_xr_e); float* xre = (float*)p;
    cudaGetSymbolAddress(&p, g_xl_p); float* xlp = (float*)p;
    cudaGetSymbolAddress(&p, g_xr_p); float* xrp = (float*)p;
    cudaGetSymbolAddress(&p, g_xl_d); float* xld = (float*)p;
    cudaGetSymbolAddress(&p, g_xr_d); float* xrd = (float*)p;
    cudaGetSymbolAddress(&p, g_g1); float* gg1 = (float*)p;
    cudaGetSymbolAddress(&p, g_g2); float* gg2 = (float*)p;

    k_prep<<<4640, 256>>>(s_dst, f_dst, x, enc_Wl, enc_Wr);
    k_scan4<<<4, 1024>>>();
    k_fill2<<<2112, 256>>>(s_src, s_dst, w_h, f_src, f_dst, w_h_a);
    k_rank<<<64, 256>>>();

    k_gemm3<<<544, 256, GEMM_SMEM>>>(Ah, Al, DI, xle, xre, xlp, xrp, 7, 1);
    k_gat_enc<<<3072, 256>>>(enc_att, enc_b, hi);

    kCP_dec<<<1376, 256>>>(hi, dec_Wl, dec_Wr, gg1, gg2);
    k_gemm3<<<512, 256, GEMM_SMEM>>>(Ah, Al, DL, xld, xrd, xld, xrd, 8, 0);
    k_post<<<4096, 256>>>(dec_att, dec_b, h, hi, bn_g, bn_b);

    k_nce<<<128, 256, NCE_SMEM>>>();
    k_rec<<<256, 256>>>(x, h, loss);
}